// round 2
// baseline (speedup 1.0000x reference)
#include <cuda_runtime.h>
#include <cstdint>
#include <cstddef>

// Problem constants
#define Hh   1024
#define Bb   16384
#define Ss   8
// Fused GEMM output width: [op1 | num1 | rz_comb(2H) | i_n | h_n] = 6H
#define NW   (6 * Hh)

// ---------------------------------------------------------------------------
// Device scratch (static allocation; no cudaMalloc allowed)
// ---------------------------------------------------------------------------
__device__ float g_Wp[(size_t)NW * Hh];           //  24 MB packed weights, NT layout [N][K]
__device__ float g_Y[(size_t)Bb * NW];            // 384 MB fused GEMM output per step

// ---------------------------------------------------------------------------
// Math helpers
// ---------------------------------------------------------------------------
__device__ __forceinline__ float gelu_exact(float x) {
    return 0.5f * x * (1.0f + erff(x * 0.70710678118654752f));
}
__device__ __forceinline__ float sigmoidf_(float x) {
    return 1.0f / (1.0f + expf(-x));
}

// ---------------------------------------------------------------------------
// Pack weights into Wpack[n][k], n in [0,6144), k in [0,1024)
//   n in [0,1024):      w_op1[k][n]                     (transpose)
//   n in [1024,2048):   w_num1[k][m]                    (transpose)
//   n in [2048,3072):   w_ih[m][k] + w_hh[m][k]         (r-gate combined)
//   n in [3072,4096):   w_ih[1024+m][k] + w_hh[1024+m][k] (z-gate combined)
//   n in [4096,5120):   w_ih[2048+m][k]                 (i_n)
//   n in [5120,6144):   w_hh[2048+m][k]                 (h_n)
// ---------------------------------------------------------------------------
__global__ void pack_weights(const float* __restrict__ w_op1,
                             const float* __restrict__ w_num1,
                             const float* __restrict__ w_ih,
                             const float* __restrict__ w_hh) {
    size_t idx = (size_t)blockIdx.x * blockDim.x + threadIdx.x;
    int n = (int)(idx >> 10);
    int k = (int)(idx & 1023);
    int m = n & 1023;
    float v;
    if (n < 1024)      v = w_op1[(size_t)k * Hh + m];
    else if (n < 2048) v = w_num1[(size_t)k * Hh + m];
    else if (n < 3072) v = w_ih[(size_t)m * Hh + k] + w_hh[(size_t)m * Hh + k];
    else if (n < 4096) v = w_ih[(size_t)(1024 + m) * Hh + k] + w_hh[(size_t)(1024 + m) * Hh + k];
    else if (n < 5120) v = w_ih[(size_t)(2048 + m) * Hh + k];
    else               v = w_hh[(size_t)(2048 + m) * Hh + k];
    g_Wp[idx] = v;
}

__global__ void copy_f32(const float* __restrict__ src, float* __restrict__ dst) {
    size_t i = (size_t)blockIdx.x * blockDim.x + threadIdx.x;
    dst[i] = src[i];
}

// ---------------------------------------------------------------------------
// SIMT GEMM (NT): C[m][n] = sum_k A[m][k] * Wp[n][k]
// A: [16384,1024] row-major (current hidden state h)
// C: g_Y [16384, 6144]
// Tile: BM=128, BN=128, BK=8, 256 threads, 8x8 per-thread micro-tile.
// ---------------------------------------------------------------------------
__global__ __launch_bounds__(256, 2)
void gemm_nt(const float* __restrict__ A) {
    const int K = Hh;
    const int N = NW;

    __shared__ float As[8][128];
    __shared__ float Bs[8][128];

    int tid = threadIdx.x;
    int m0 = blockIdx.y * 128;
    int n0 = blockIdx.x * 128;

    int loadRow = tid >> 1;          // 0..127
    int loadCol = (tid & 1) << 2;    // 0 or 4

    const float* Aptr = A + (size_t)(m0 + loadRow) * K + loadCol;
    const float* Bptr = g_Wp + (size_t)(n0 + loadRow) * K + loadCol;

    int ty = tid >> 4;   // 0..15 -> row group
    int tx = tid & 15;   // 0..15 -> col group

    float acc[8][8];
#pragma unroll
    for (int i = 0; i < 8; i++)
#pragma unroll
        for (int j = 0; j < 8; j++) acc[i][j] = 0.0f;

    for (int k0 = 0; k0 < K; k0 += 8) {
        float4 a4 = *(const float4*)(Aptr + k0);
        float4 b4 = *(const float4*)(Bptr + k0);
        __syncthreads();
        As[loadCol + 0][loadRow] = a4.x;
        As[loadCol + 1][loadRow] = a4.y;
        As[loadCol + 2][loadRow] = a4.z;
        As[loadCol + 3][loadRow] = a4.w;
        Bs[loadCol + 0][loadRow] = b4.x;
        Bs[loadCol + 1][loadRow] = b4.y;
        Bs[loadCol + 2][loadRow] = b4.z;
        Bs[loadCol + 3][loadRow] = b4.w;
        __syncthreads();

#pragma unroll
        for (int kk = 0; kk < 8; kk++) {
            float a[8], b[8];
            *(float4*)(a)     = *(const float4*)&As[kk][ty * 8];
            *(float4*)(a + 4) = *(const float4*)&As[kk][ty * 8 + 4];
            *(float4*)(b)     = *(const float4*)&Bs[kk][tx * 8];
            *(float4*)(b + 4) = *(const float4*)&Bs[kk][tx * 8 + 4];
#pragma unroll
            for (int i = 0; i < 8; i++)
#pragma unroll
                for (int j = 0; j < 8; j++)
                    acc[i][j] = fmaf(a[i], b[j], acc[i][j]);
        }
    }

#pragma unroll
    for (int i = 0; i < 8; i++) {
        size_t crow = (size_t)(m0 + ty * 8 + i) * N + (n0 + tx * 8);
#pragma unroll
        for (int j4 = 0; j4 < 2; j4++) {
            float4 v;
            v.x = acc[i][j4 * 4 + 0];
            v.y = acc[i][j4 * 4 + 1];
            v.z = acc[i][j4 * 4 + 2];
            v.w = acc[i][j4 * 4 + 3];
            *(float4*)&g_Y[crow + j4 * 4] = v;
        }
    }
}

// ---------------------------------------------------------------------------
// Heads: per batch row, GELU then tiny matmuls to 5 + 1 outputs.
// One block (256 threads) per row.
// ---------------------------------------------------------------------------
__global__ __launch_bounds__(256)
void heads_kernel(const float* __restrict__ b_op1,
                  const float* __restrict__ b_num1,
                  const float* __restrict__ w_op2,   // [H,5]
                  const float* __restrict__ b_op2,   // [5]
                  const float* __restrict__ w_num2,  // [H,1]
                  const float* __restrict__ b_num2,  // [1]
                  float* __restrict__ ops_out,       // [B,5] (pre-offset for step)
                  float* __restrict__ nums_out) {    // [B]   (pre-offset for step)
    int row = blockIdx.x;
    int t = threadIdx.x;
    const float* y = g_Y + (size_t)row * NW;

    float acc[5] = {0.f, 0.f, 0.f, 0.f, 0.f};
    float accn = 0.f;

#pragma unroll
    for (int it = 0; it < Hh / 256; it++) {
        int c = t + it * 256;
        float a = gelu_exact(y[c] + b_op1[c]);
        const float* wr = w_op2 + (size_t)c * 5;
        acc[0] += a * wr[0];
        acc[1] += a * wr[1];
        acc[2] += a * wr[2];
        acc[3] += a * wr[3];
        acc[4] += a * wr[4];
        float an = gelu_exact(y[Hh + c] + b_num1[c]);
        accn += an * w_num2[c];
    }

    // warp reduce 6 values
#pragma unroll
    for (int off = 16; off > 0; off >>= 1) {
#pragma unroll
        for (int q = 0; q < 5; q++)
            acc[q] += __shfl_down_sync(0xffffffffu, acc[q], off);
        accn += __shfl_down_sync(0xffffffffu, accn, off);
    }

    __shared__ float red[8][6];
    int warp = t >> 5, lane = t & 31;
    if (lane == 0) {
#pragma unroll
        for (int q = 0; q < 5; q++) red[warp][q] = acc[q];
        red[warp][5] = accn;
    }
    __syncthreads();
    if (t < 6) {
        float s = 0.f;
#pragma unroll
        for (int w = 0; w < 8; w++) s += red[w][t];
        if (t < 5) ops_out[(size_t)row * 5 + t] = s + b_op2[t];
        else       nums_out[row] = s + b_num2[0];
    }
}

// ---------------------------------------------------------------------------
// GRU combine: reads combined-gate columns from g_Y, h_in, writes h_out.
//   r = sigmoid(y_rz[0..H)   + b_ih[j]      + b_hh[j])
//   z = sigmoid(y_rz[H..2H)  + b_ih[H+j]    + b_hh[H+j])
//   n = tanh(y_in + b_ih[2H+j] + r * (y_hn + b_hh[2H+j]))
//   h' = (1-z)*n + z*h
// ---------------------------------------------------------------------------
__global__ __launch_bounds__(256)
void gru_kernel(const float* __restrict__ h_in,
                const float* __restrict__ b_ih,
                const float* __restrict__ b_hh,
                float* __restrict__ h_out) {
    size_t idx = (size_t)blockIdx.x * 256 + threadIdx.x;  // over B*H
    int row = (int)(idx >> 10);
    int j = (int)(idx & 1023);
    const float* y = g_Y + (size_t)row * NW;

    float pre_r = y[2048 + j] + b_ih[j] + b_hh[j];
    float pre_z = y[3072 + j] + b_ih[1024 + j] + b_hh[1024 + j];
    float i_n   = y[4096 + j] + b_ih[2048 + j];
    float h_n   = y[5120 + j] + b_hh[2048 + j];

    float r = sigmoidf_(pre_r);
    float z = sigmoidf_(pre_z);
    float n = tanhf(i_n + r * h_n);
    float hold = h_in[idx];
    h_out[idx] = (1.0f - z) * n + z * hold;
}

// ---------------------------------------------------------------------------
// Launch
// ---------------------------------------------------------------------------
extern "C" void kernel_launch(void* const* d_in, const int* in_sizes, int n_in,
                              void* d_out, int out_size) {
    const float* x      = (const float*)d_in[0];
    // d_in[1] = num_steps (int scalar on device) — fixed at 8 for this problem
    const float* w_op1  = (const float*)d_in[2];
    const float* b_op1  = (const float*)d_in[3];
    const float* w_op2  = (const float*)d_in[4];
    const float* b_op2  = (const float*)d_in[5];
    const float* w_num1 = (const float*)d_in[6];
    const float* b_num1 = (const float*)d_in[7];
    const float* w_num2 = (const float*)d_in[8];
    const float* b_num2 = (const float*)d_in[9];
    const float* w_ih   = (const float*)d_in[10];
    const float* b_ih   = (const float*)d_in[11];
    const float* w_hh   = (const float*)d_in[12];
    const float* b_hh   = (const float*)d_in[13];

    float* out = (float*)d_out;
    // Output layout: [final_state (B*H) | ops (S*B*5) | nums (S*B) | states (S*B*H)]
    float* final_state = out;
    float* ops    = out + (size_t)Bb * Hh;
    float* nums   = ops + (size_t)Ss * Bb * 5;
    float* states = nums + (size_t)Ss * Bb;

    // 1) Pack weights (NT layout, gates r/z combined since input==hidden)
    pack_weights<<<((size_t)NW * Hh) / 256, 256>>>(w_op1, w_num1, w_ih, w_hh);

    // 2) states[0] = x  (pre-update hidden state of step 0)
    copy_f32<<<((size_t)Bb * Hh) / 256, 256>>>(x, states);

    // 3) 8 sequential steps; hidden state chained through the states output region
    for (int s = 0; s < Ss; s++) {
        const float* h = states + (size_t)s * Bb * Hh;

        dim3 ggrid(NW / 128, Bb / 128);  // (48, 128)
        gemm_nt<<<ggrid, 256>>>(h);

        heads_kernel<<<Bb, 256>>>(b_op1, b_num1, w_op2, b_op2, w_num2, b_num2,
                                  ops + (size_t)s * Bb * 5, nums + (size_t)s * Bb);

        float* h_out = (s == Ss - 1) ? final_state
                                     : states + (size_t)(s + 1) * Bb * Hh;
        gru_kernel<<<((size_t)Bb * Hh) / 256, 256>>>(h, b_ih, b_hh, h_out);
    }
}

// round 4
// speedup vs baseline: 1.7740x; 1.7740x over previous
#include <cuda_runtime.h>
#include <cuda_bf16.h>
#include <cstdint>
#include <cstddef>

// Problem constants
#define Hh   1024
#define Bb   16384
#define Ss   8
#define NW   6144          // fused GEMM width: [op1 | num1 | rz_r | rz_z | i_n | h_n]
#define KTOT 3072          // split-K: [Ahi*Whi | Ahi*Wlo | Alo*Whi]
#define KA   2048          // physical A: [Ahi | Alo]
#define NCHUNK 48          // KTOT / 64

#define STAGES      3
#define STAGE_BYTES 32768  // A 128x64 bf16 (16KB) + B 128x64 bf16 (16KB)
#define SMEM_TOT    (STAGES * STAGE_BYTES)

// ---------------------------------------------------------------------------
// Device scratch
// ---------------------------------------------------------------------------
__device__ float          g_Y[(size_t)Bb * NW];      // 384 MB GEMM out per step
__device__ __nv_bfloat16  g_W2[(size_t)NW * KTOT];   // 37.7 MB packed split weights
__device__ __nv_bfloat16  g_A2[(size_t)Bb * KA];     // 64 MB split activations

// ---------------------------------------------------------------------------
// Helpers
// ---------------------------------------------------------------------------
__device__ __forceinline__ float gelu_exact(float x) {
    return 0.5f * x * (1.0f + erff(x * 0.70710678118654752f));
}
__device__ __forceinline__ float sigmoidf_(float x) {
    return 1.0f / (1.0f + expf(-x));
}
__device__ __forceinline__ uint32_t smem_u32(const void* p) {
    uint32_t a;
    asm("{ .reg .u64 t; cvta.to.shared.u64 t, %1; cvt.u32.u64 %0, t; }" : "=r"(a) : "l"(p));
    return a;
}
__device__ __forceinline__ void cpasync16(uint32_t dst, const void* src) {
    asm volatile("cp.async.cg.shared.global [%0], [%1], 16;" :: "r"(dst), "l"(src) : "memory");
}
__device__ __forceinline__ void cp_commit() {
    asm volatile("cp.async.commit_group;" ::: "memory");
}
template <int N>
__device__ __forceinline__ void cp_wait() {
    asm volatile("cp.async.wait_group %0;" :: "n"(N) : "memory");
}
__device__ __forceinline__ void ldsm4(uint32_t* r, uint32_t addr) {
    asm volatile("ldmatrix.sync.aligned.m8n8.x4.shared.b16 {%0,%1,%2,%3}, [%4];"
                 : "=r"(r[0]), "=r"(r[1]), "=r"(r[2]), "=r"(r[3]) : "r"(addr));
}
__device__ __forceinline__ void mma_bf16(float* c, const uint32_t* a, const uint32_t* b) {
    asm volatile(
        "mma.sync.aligned.m16n8k16.row.col.f32.bf16.bf16.f32 "
        "{%0,%1,%2,%3}, {%4,%5,%6,%7}, {%8,%9}, {%0,%1,%2,%3};"
        : "+f"(c[0]), "+f"(c[1]), "+f"(c[2]), "+f"(c[3])
        : "r"(a[0]), "r"(a[1]), "r"(a[2]), "r"(a[3]), "r"(b[0]), "r"(b[1]));
}
__device__ __forceinline__ uint32_t sw128(uint32_t off) {
    return off ^ ((off >> 3) & 0x70);
}

// ---------------------------------------------------------------------------
// Pack split weights g_W2[n][k]: k slots [Whi | Wlo | Whi]
// ---------------------------------------------------------------------------
__global__ void pack_w2(const float* __restrict__ w_op1, const float* __restrict__ w_num1,
                        const float* __restrict__ w_ih, const float* __restrict__ w_hh) {
    size_t idx = (size_t)blockIdx.x * 256 + threadIdx.x;   // over NW*1024
    int n = (int)(idx >> 10);
    int kk = (int)(idx & 1023);
    int m = n & 1023;
    float v;
    if (n < 1024)      v = w_op1[(size_t)kk * Hh + m];
    else if (n < 2048) v = w_num1[(size_t)kk * Hh + m];
    else if (n < 3072) v = w_ih[(size_t)m * Hh + kk] + w_hh[(size_t)m * Hh + kk];
    else if (n < 4096) v = w_ih[(size_t)(1024 + m) * Hh + kk] + w_hh[(size_t)(1024 + m) * Hh + kk];
    else if (n < 5120) v = w_ih[(size_t)(2048 + m) * Hh + kk];
    else               v = w_hh[(size_t)(2048 + m) * Hh + kk];
    __nv_bfloat16 hi = __float2bfloat16(v);
    __nv_bfloat16 lo = __float2bfloat16(v - __bfloat162float(hi));
    size_t base = (size_t)n * KTOT;
    g_W2[base + kk]        = hi;
    g_W2[base + 1024 + kk] = lo;
    g_W2[base + 2048 + kk] = hi;
}

// states[0] = x, and split x -> g_A2
__global__ void convert_x(const float* __restrict__ x, float* __restrict__ states0) {
    size_t idx = (size_t)blockIdx.x * 256 + threadIdx.x;
    float h = x[idx];
    states0[idx] = h;
    int row = (int)(idx >> 10), j = (int)(idx & 1023);
    __nv_bfloat16 hi = __float2bfloat16(h);
    __nv_bfloat16 lo = __float2bfloat16(h - __bfloat162float(hi));
    g_A2[(size_t)row * KA + j]        = hi;
    g_A2[(size_t)row * KA + 1024 + j] = lo;
}

// ---------------------------------------------------------------------------
// HMMA GEMM: Y[m][n] = sum_k A2[m][k] * W2[n][k]  (bf16 in, fp32 accum/out)
// BM=128, BN=128, BK=64. 256 threads = 8 warps (2 m x 4 n), warp tile 64x32.
// 3-stage cp.async pipeline; SW128-swizzled smem; ldmatrix; m16n8k16 mma.
// ---------------------------------------------------------------------------
__global__ void __launch_bounds__(256, 1) gemm_mma() {
    extern __shared__ char smem[];
    uint32_t sb = smem_u32(smem);
    int tid = threadIdx.x;
    int lane = tid & 31;
    int wid = tid >> 5;
    int n0 = blockIdx.x * 128;
    int m0 = blockIdx.y * 128;

    // ---- per-thread cp.async assignments: 4 A segs + 4 B segs (16B each) ----
    uint32_t dA[4], dB[4];
    const char* pA[4];
    const char* pB[4];
#pragma unroll
    for (int i = 0; i < 4; i++) {
        int seg = tid + i * 256;           // 0..1023
        int row = seg >> 3, s8 = seg & 7;
        uint32_t off = row * 128 + s8 * 16;
        dA[i] = sw128(off);
        dB[i] = 16384 + sw128(off);
        pA[i] = (const char*)(g_A2 + (size_t)(m0 + row) * KA) + s8 * 16;
        pB[i] = (const char*)(g_W2 + (size_t)(n0 + row) * KTOT) + s8 * 16;
    }

    // ---- precomputed swizzled ldmatrix offsets (stage-relative) ----
    int wm = (wid >> 2) * 64;   // warp m offset: 0 or 64
    int wn = (wid & 3) * 32;    // warp n offset: 0,32,64,96
    uint32_t aoff[4][4], boff[4][2];
#pragma unroll
    for (int ks = 0; ks < 4; ks++) {
#pragma unroll
        for (int mi = 0; mi < 4; mi++) {
            uint32_t off = (uint32_t)(wm + mi * 16 + (lane & 15)) * 128
                         + ks * 32 + ((lane >> 4) << 4);
            aoff[ks][mi] = sw128(off);
        }
#pragma unroll
        for (int nb = 0; nb < 2; nb++) {
            uint32_t rown = wn + nb * 16 + ((lane >> 4) & 1) * 8 + (lane & 7);
            uint32_t off = rown * 128 + ks * 32 + ((lane >> 3) & 1) * 16;
            boff[ks][nb] = 16384 + sw128(off);
        }
    }

    float cc[4][4][4];
#pragma unroll
    for (int mi = 0; mi < 4; mi++)
#pragma unroll
        for (int ni = 0; ni < 4; ni++)
#pragma unroll
            for (int q = 0; q < 4; q++) cc[mi][ni][q] = 0.0f;

    auto load_stage = [&](int st, int c) {
        uint32_t stb = sb + st * STAGE_BYTES;
        int akb = (c < 16 ? c : c - 16) * 128;   // A byte offset for this chunk
        int wkb = c * 128;                       // B byte offset
#pragma unroll
        for (int i = 0; i < 4; i++) cpasync16(stb + dA[i], pA[i] + akb);
#pragma unroll
        for (int i = 0; i < 4; i++) cpasync16(stb + dB[i], pB[i] + wkb);
    };

    // ---- prologue ----
    load_stage(0, 0);
    cp_commit();
    load_stage(1, 1);
    cp_commit();

    // ---- main loop ----
    for (int c = 0; c < NCHUNK; c++) {
        cp_wait<1>();
        __syncthreads();
        if (c + 2 < NCHUNK) load_stage((c + 2) % STAGES, c + 2);
        cp_commit();

        uint32_t stb = sb + (c % STAGES) * STAGE_BYTES;
#pragma unroll
        for (int ks = 0; ks < 4; ks++) {
            uint32_t a[4][4];
#pragma unroll
            for (int mi = 0; mi < 4; mi++) ldsm4(a[mi], stb + aoff[ks][mi]);
            uint32_t b[4][2];
#pragma unroll
            for (int nb = 0; nb < 2; nb++) {
                uint32_t r[4];
                ldsm4(r, stb + boff[ks][nb]);
                b[nb * 2][0] = r[0]; b[nb * 2][1] = r[1];
                b[nb * 2 + 1][0] = r[2]; b[nb * 2 + 1][1] = r[3];
            }
#pragma unroll
            for (int mi = 0; mi < 4; mi++)
#pragma unroll
                for (int ni = 0; ni < 4; ni++)
                    mma_bf16(cc[mi][ni], a[mi], b[ni]);
        }
        __syncthreads();
    }

    // ---- epilogue: registers -> g_Y (fp32) ----
    int mrow = m0 + wm + (lane >> 2);
    int ncol = n0 + wn + (lane & 3) * 2;
#pragma unroll
    for (int mi = 0; mi < 4; mi++) {
#pragma unroll
        for (int ni = 0; ni < 4; ni++) {
            float2 v0 = make_float2(cc[mi][ni][0], cc[mi][ni][1]);
            float2 v1 = make_float2(cc[mi][ni][2], cc[mi][ni][3]);
            *(float2*)&g_Y[(size_t)(mrow + mi * 16) * NW + ncol + ni * 8] = v0;
            *(float2*)&g_Y[(size_t)(mrow + mi * 16 + 8) * NW + ncol + ni * 8] = v1;
        }
    }
}

// ---------------------------------------------------------------------------
// Heads: per batch row, GELU then tiny matmuls to 5 + 1 outputs.
// ---------------------------------------------------------------------------
__global__ __launch_bounds__(256)
void heads_kernel(const float* __restrict__ b_op1, const float* __restrict__ b_num1,
                  const float* __restrict__ w_op2, const float* __restrict__ b_op2,
                  const float* __restrict__ w_num2, const float* __restrict__ b_num2,
                  float* __restrict__ ops_out, float* __restrict__ nums_out) {
    int row = blockIdx.x;
    int t = threadIdx.x;
    const float* y = g_Y + (size_t)row * NW;

    float acc[5] = {0.f, 0.f, 0.f, 0.f, 0.f};
    float accn = 0.f;
#pragma unroll
    for (int it = 0; it < Hh / 256; it++) {
        int c = t + it * 256;
        float a = gelu_exact(y[c] + b_op1[c]);
        const float* wr = w_op2 + (size_t)c * 5;
        acc[0] += a * wr[0];
        acc[1] += a * wr[1];
        acc[2] += a * wr[2];
        acc[3] += a * wr[3];
        acc[4] += a * wr[4];
        float an = gelu_exact(y[Hh + c] + b_num1[c]);
        accn += an * w_num2[c];
    }
#pragma unroll
    for (int off = 16; off > 0; off >>= 1) {
#pragma unroll
        for (int q = 0; q < 5; q++) acc[q] += __shfl_down_sync(0xffffffffu, acc[q], off);
        accn += __shfl_down_sync(0xffffffffu, accn, off);
    }
    __shared__ float red[8][6];
    int warp = t >> 5, lane = t & 31;
    if (lane == 0) {
#pragma unroll
        for (int q = 0; q < 5; q++) red[warp][q] = acc[q];
        red[warp][5] = accn;
    }
    __syncthreads();
    if (t < 6) {
        float s = 0.f;
#pragma unroll
        for (int w = 0; w < 8; w++) s += red[w][t];
        if (t < 5) ops_out[(size_t)row * 5 + t] = s + b_op2[t];
        else       nums_out[row] = s + b_num2[0];
    }
}

// ---------------------------------------------------------------------------
// GRU combine; also emits split bf16 activations for the next step's GEMM.
// ---------------------------------------------------------------------------
__global__ __launch_bounds__(256)
void gru_kernel(const float* __restrict__ h_in, const float* __restrict__ b_ih,
                const float* __restrict__ b_hh, float* __restrict__ h_out, int write_a2) {
    size_t idx = (size_t)blockIdx.x * 256 + threadIdx.x;
    int row = (int)(idx >> 10);
    int j = (int)(idx & 1023);
    const float* y = g_Y + (size_t)row * NW;

    float pre_r = y[2048 + j] + b_ih[j] + b_hh[j];
    float pre_z = y[3072 + j] + b_ih[1024 + j] + b_hh[1024 + j];
    float i_n   = y[4096 + j] + b_ih[2048 + j];
    float h_n   = y[5120 + j] + b_hh[2048 + j];

    float r = sigmoidf_(pre_r);
    float z = sigmoidf_(pre_z);
    float n = tanhf(i_n + r * h_n);
    float hnew = (1.0f - z) * n + z * h_in[idx];
    h_out[idx] = hnew;
    if (write_a2) {
        __nv_bfloat16 hi = __float2bfloat16(hnew);
        __nv_bfloat16 lo = __float2bfloat16(hnew - __bfloat162float(hi));
        g_A2[(size_t)row * KA + j]        = hi;
        g_A2[(size_t)row * KA + 1024 + j] = lo;
    }
}

// ---------------------------------------------------------------------------
// Launch
// ---------------------------------------------------------------------------
extern "C" void kernel_launch(void* const* d_in, const int* in_sizes, int n_in,
                              void* d_out, int out_size) {
    const float* x      = (const float*)d_in[0];
    const float* w_op1  = (const float*)d_in[2];
    const float* b_op1  = (const float*)d_in[3];
    const float* w_op2  = (const float*)d_in[4];
    const float* b_op2  = (const float*)d_in[5];
    const float* w_num1 = (const float*)d_in[6];
    const float* b_num1 = (const float*)d_in[7];
    const float* w_num2 = (const float*)d_in[8];
    const float* b_num2 = (const float*)d_in[9];
    const float* w_ih   = (const float*)d_in[10];
    const float* b_ih   = (const float*)d_in[11];
    const float* w_hh   = (const float*)d_in[12];
    const float* b_hh   = (const float*)d_in[13];

    float* out = (float*)d_out;
    float* final_state = out;
    float* ops    = out + (size_t)Bb * Hh;
    float* nums   = ops + (size_t)Ss * Bb * 5;
    float* states = nums + (size_t)Ss * Bb;

    static bool attr_set = false;
    if (!attr_set) {
        cudaFuncSetAttribute(gemm_mma, cudaFuncAttributeMaxDynamicSharedMemorySize, SMEM_TOT);
        attr_set = true;
    }

    pack_w2<<<(NW * 1024) / 256, 256>>>(w_op1, w_num1, w_ih, w_hh);
    convert_x<<<(Bb * Hh) / 256, 256>>>(x, states);

    for (int s = 0; s < Ss; s++) {
        dim3 ggrid(NW / 128, Bb / 128);   // (48, 128)
        gemm_mma<<<ggrid, 256, SMEM_TOT>>>();

        heads_kernel<<<Bb, 256>>>(b_op1, b_num1, w_op2, b_op2, w_num2, b_num2,
                                  ops + (size_t)s * Bb * 5, nums + (size_t)s * Bb);

        const float* h = states + (size_t)s * Bb * Hh;
        float* h_out = (s == Ss - 1) ? final_state
                                     : states + (size_t)(s + 1) * Bb * Hh;
        gru_kernel<<<(Bb * Hh) / 256, 256>>>(h, b_ih, b_hh, h_out, (s == Ss - 1) ? 0 : 1);
    }
}

// round 6
// speedup vs baseline: 2.9979x; 1.6899x over previous
#include <cuda_runtime.h>
#include <cuda_bf16.h>
#include <cstdint>
#include <cstddef>

// Problem constants
#define Hh   1024
#define Bb   16384
#define Ss   8
#define NW   6144          // fused GEMM width: [op1 | num1 | rz_r | rz_z | i_n | h_n]
#define KTOT 3072          // split-K: [Ahi*Whi | Ahi*Wlo | Alo*Whi]
#define KA   2048          // physical A: [Ahi | Alo]
#define NCHUNK 48          // KTOT / 64

#define BM 128
#define BN 256
#define STAGES      3
#define STAGE_BYTES 49152  // A 128x64 bf16 (16KB) + B 256x64 bf16 (32KB)
#define SMEM_TOT    (STAGES * STAGE_BYTES)

// ---------------------------------------------------------------------------
// Device scratch
// ---------------------------------------------------------------------------
__device__ float          g_Y[(size_t)Bb * NW];      // 384 MB GEMM out per step
__device__ __nv_bfloat16  g_W2[(size_t)NW * KTOT];   // 37.7 MB packed split weights
__device__ __nv_bfloat16  g_A2[(size_t)Bb * KA];     // 64 MB split activations
__device__ float          g_Wop2t[5 * Hh];           // transposed op head weights

// ---------------------------------------------------------------------------
// Helpers
// ---------------------------------------------------------------------------
__device__ __forceinline__ float gelu_exact(float x) {
    return 0.5f * x * (1.0f + erff(x * 0.70710678118654752f));
}
__device__ __forceinline__ float sigmoidf_(float x) {
    return 1.0f / (1.0f + expf(-x));
}
__device__ __forceinline__ uint32_t smem_u32(const void* p) {
    uint32_t a;
    asm("{ .reg .u64 t; cvta.to.shared.u64 t, %1; cvt.u32.u64 %0, t; }" : "=r"(a) : "l"(p));
    return a;
}
__device__ __forceinline__ void cpasync16(uint32_t dst, const void* src) {
    asm volatile("cp.async.cg.shared.global [%0], [%1], 16;" :: "r"(dst), "l"(src) : "memory");
}
__device__ __forceinline__ void cp_commit() {
    asm volatile("cp.async.commit_group;" ::: "memory");
}
template <int N>
__device__ __forceinline__ void cp_wait() {
    asm volatile("cp.async.wait_group %0;" :: "n"(N) : "memory");
}
__device__ __forceinline__ void ldsm4(uint32_t* r, uint32_t addr) {
    asm volatile("ldmatrix.sync.aligned.m8n8.x4.shared.b16 {%0,%1,%2,%3}, [%4];"
                 : "=r"(r[0]), "=r"(r[1]), "=r"(r[2]), "=r"(r[3]) : "r"(addr));
}
__device__ __forceinline__ void mma_bf16(float* c, const uint32_t* a, const uint32_t* b) {
    asm volatile(
        "mma.sync.aligned.m16n8k16.row.col.f32.bf16.bf16.f32 "
        "{%0,%1,%2,%3}, {%4,%5,%6,%7}, {%8,%9}, {%0,%1,%2,%3};"
        : "+f"(c[0]), "+f"(c[1]), "+f"(c[2]), "+f"(c[3])
        : "r"(a[0]), "r"(a[1]), "r"(a[2]), "r"(a[3]), "r"(b[0]), "r"(b[1]));
}
__device__ __forceinline__ uint32_t sw128(uint32_t off) {
    return off ^ ((off >> 3) & 0x70);
}

// ---------------------------------------------------------------------------
// Pack split weights g_W2[n][k]: k slots [Whi | Wlo | Whi]
// ---------------------------------------------------------------------------
__global__ void pack_w2(const float* __restrict__ w_op1, const float* __restrict__ w_num1,
                        const float* __restrict__ w_ih, const float* __restrict__ w_hh) {
    size_t idx = (size_t)blockIdx.x * 256 + threadIdx.x;   // over NW*1024
    int n = (int)(idx >> 10);
    int kk = (int)(idx & 1023);
    int m = n & 1023;
    float v;
    if (n < 1024)      v = w_op1[(size_t)kk * Hh + m];
    else if (n < 2048) v = w_num1[(size_t)kk * Hh + m];
    else if (n < 3072) v = w_ih[(size_t)m * Hh + kk] + w_hh[(size_t)m * Hh + kk];
    else if (n < 4096) v = w_ih[(size_t)(1024 + m) * Hh + kk] + w_hh[(size_t)(1024 + m) * Hh + kk];
    else if (n < 5120) v = w_ih[(size_t)(2048 + m) * Hh + kk];
    else               v = w_hh[(size_t)(2048 + m) * Hh + kk];
    __nv_bfloat16 hi = __float2bfloat16(v);
    __nv_bfloat16 lo = __float2bfloat16(v - __bfloat162float(hi));
    size_t base = (size_t)n * KTOT;
    g_W2[base + kk]        = hi;
    g_W2[base + 1024 + kk] = lo;
    g_W2[base + 2048 + kk] = hi;
}

// transpose w_op2 [H,5] -> g_Wop2t [5,H]
__global__ void pack_hw(const float* __restrict__ w_op2) {
    int idx = blockIdx.x * 256 + threadIdx.x;   // 0..5119
    int q = idx >> 10, c = idx & 1023;
    g_Wop2t[idx] = w_op2[(size_t)c * 5 + q];
}

// states[0] = x, and split x -> g_A2
__global__ void convert_x(const float* __restrict__ x, float* __restrict__ states0) {
    size_t idx = (size_t)blockIdx.x * 256 + threadIdx.x;
    float h = x[idx];
    states0[idx] = h;
    int row = (int)(idx >> 10), j = (int)(idx & 1023);
    __nv_bfloat16 hi = __float2bfloat16(h);
    __nv_bfloat16 lo = __float2bfloat16(h - __bfloat162float(hi));
    g_A2[(size_t)row * KA + j]        = hi;
    g_A2[(size_t)row * KA + 1024 + j] = lo;
}

// ---------------------------------------------------------------------------
// HMMA GEMM: Y[m][n] = sum_k A2[m][k] * W2[n][k]  (bf16 in, fp32 accum/out)
// BM=128, BN=256, BK=64. 256 threads = 8 warps (2 m x 4 n), warp tile 64x64.
// 3-stage cp.async pipeline, single __syncthreads per chunk.
// ---------------------------------------------------------------------------
__global__ void __launch_bounds__(256, 1) gemm_mma() {
    extern __shared__ char smem[];
    uint32_t sb = smem_u32(smem);
    int tid = threadIdx.x;
    int lane = tid & 31;
    int wid = tid >> 5;
    int n0 = blockIdx.x * BN;
    int m0 = blockIdx.y * BM;

    // ---- cp.async bases (strided across i) ----
    int lrow = tid >> 3;            // 0..31
    int ls8 = tid & 7;
    uint32_t d0 = sw128((uint32_t)lrow * 128 + ls8 * 16);
    const char* pA0 = (const char*)(g_A2 + (size_t)(m0 + lrow) * KA) + ls8 * 16;
    const char* pB0 = (const char*)(g_W2 + (size_t)(n0 + lrow) * KTOT) + ls8 * 16;

    // ---- ldmatrix base offsets (ks=0); sw(off + ks*32) == sw(off) ^ (ks*32) ----
    int wm = (wid >> 2) * 64;       // 0 or 64
    int wn = (wid & 3) * 64;        // 0,64,128,192
    uint32_t aoffb[4], boffb[4];
#pragma unroll
    for (int mi = 0; mi < 4; mi++)
        aoffb[mi] = sw128((uint32_t)(wm + mi * 16 + (lane & 15)) * 128 + ((lane >> 4) << 4));
#pragma unroll
    for (int nb = 0; nb < 4; nb++) {
        uint32_t rown = wn + nb * 16 + ((lane >> 4) & 1) * 8 + (lane & 7);
        boffb[nb] = sw128(rown * 128 + ((lane >> 3) & 1) * 16);
    }

    float cc[4][8][4];
#pragma unroll
    for (int mi = 0; mi < 4; mi++)
#pragma unroll
        for (int ni = 0; ni < 8; ni++)
#pragma unroll
            for (int q = 0; q < 4; q++) cc[mi][ni][q] = 0.0f;

    auto load_stage = [&](int st, int c) {
        uint32_t stb = sb + st * STAGE_BYTES;
        int akb = (c < 16 ? c : c - 16) * 128;   // A byte offset (hi for c<32, lo after)
        int wkb = c * 128;                       // B byte offset
#pragma unroll
        for (int i = 0; i < 4; i++)
            cpasync16(stb + d0 + 4096 * i, pA0 + (size_t)i * 32 * (KA * 2) + akb);
#pragma unroll
        for (int i = 0; i < 8; i++)
            cpasync16(stb + 16384 + d0 + 4096 * i, pB0 + (size_t)i * 32 * (KTOT * 2) + wkb);
    };

    // ---- prologue ----
    load_stage(0, 0);
    cp_commit();
    load_stage(1, 1);
    cp_commit();

    // ---- main loop: one barrier per chunk ----
    for (int c = 0; c < NCHUNK; c++) {
        cp_wait<1>();
        __syncthreads();
        if (c + 2 < NCHUNK) load_stage((c + 2) % STAGES, c + 2);
        cp_commit();

        uint32_t stb = sb + (c % STAGES) * STAGE_BYTES;
#pragma unroll
        for (int ks = 0; ks < 4; ks++) {
            uint32_t kx = (uint32_t)ks * 32;
            uint32_t a[4][4];
#pragma unroll
            for (int mi = 0; mi < 4; mi++) ldsm4(a[mi], stb + (aoffb[mi] ^ kx));
            uint32_t b[8][2];
#pragma unroll
            for (int nb = 0; nb < 4; nb++) {
                uint32_t r[4];
                ldsm4(r, stb + 16384 + (boffb[nb] ^ kx));
                b[nb * 2][0] = r[0]; b[nb * 2][1] = r[1];
                b[nb * 2 + 1][0] = r[2]; b[nb * 2 + 1][1] = r[3];
            }
#pragma unroll
            for (int mi = 0; mi < 4; mi++)
#pragma unroll
                for (int ni = 0; ni < 8; ni++)
                    mma_bf16(cc[mi][ni], a[mi], b[ni]);
        }
    }

    // ---- epilogue: registers -> g_Y (fp32) ----
    int mrow = m0 + wm + (lane >> 2);
    int ncol = n0 + wn + (lane & 3) * 2;
#pragma unroll
    for (int mi = 0; mi < 4; mi++) {
#pragma unroll
        for (int ni = 0; ni < 8; ni++) {
            float2 v0 = make_float2(cc[mi][ni][0], cc[mi][ni][1]);
            float2 v1 = make_float2(cc[mi][ni][2], cc[mi][ni][3]);
            *(float2*)&g_Y[(size_t)(mrow + mi * 16) * NW + ncol + ni * 8] = v0;
            *(float2*)&g_Y[(size_t)(mrow + mi * 16 + 8) * NW + ncol + ni * 8] = v1;
        }
    }
}

// ---------------------------------------------------------------------------
// Heads: per batch row, GELU then tiny matmuls to 5 + 1 outputs.
// ---------------------------------------------------------------------------
__global__ __launch_bounds__(256)
void heads_kernel(const float* __restrict__ b_op1, const float* __restrict__ b_num1,
                  const float* __restrict__ b_op2,
                  const float* __restrict__ w_num2, const float* __restrict__ b_num2,
                  float* __restrict__ ops_out, float* __restrict__ nums_out) {
    int row = blockIdx.x;
    int t = threadIdx.x;
    const float* y = g_Y + (size_t)row * NW;

    float acc[5] = {0.f, 0.f, 0.f, 0.f, 0.f};
    float accn = 0.f;
#pragma unroll
    for (int it = 0; it < Hh / 256; it++) {
        int c = t + it * 256;
        float a = gelu_exact(y[c] + b_op1[c]);
#pragma unroll
        for (int q = 0; q < 5; q++) acc[q] += a * g_Wop2t[q * Hh + c];
        float an = gelu_exact(y[Hh + c] + b_num1[c]);
        accn += an * w_num2[c];
    }
#pragma unroll
    for (int off = 16; off > 0; off >>= 1) {
#pragma unroll
        for (int q = 0; q < 5; q++) acc[q] += __shfl_down_sync(0xffffffffu, acc[q], off);
        accn += __shfl_down_sync(0xffffffffu, accn, off);
    }
    __shared__ float red[8][6];
    int warp = t >> 5, lane = t & 31;
    if (lane == 0) {
#pragma unroll
        for (int q = 0; q < 5; q++) red[warp][q] = acc[q];
        red[warp][5] = accn;
    }
    __syncthreads();
    if (t < 6) {
        float s = 0.f;
#pragma unroll
        for (int w = 0; w < 8; w++) s += red[w][t];
        if (t < 5) ops_out[(size_t)row * 5 + t] = s + b_op2[t];
        else       nums_out[row] = s + b_num2[0];
    }
}

// ---------------------------------------------------------------------------
// GRU combine; also emits split bf16 activations for the next step's GEMM.
// ---------------------------------------------------------------------------
__global__ __launch_bounds__(256)
void gru_kernel(const float* __restrict__ h_in, const float* __restrict__ b_ih,
                const float* __restrict__ b_hh, float* __restrict__ h_out, int write_a2) {
    size_t idx = (size_t)blockIdx.x * 256 + threadIdx.x;
    int row = (int)(idx >> 10);
    int j = (int)(idx & 1023);
    const float* y = g_Y + (size_t)row * NW;

    float pre_r = y[2048 + j] + b_ih[j] + b_hh[j];
    float pre_z = y[3072 + j] + b_ih[1024 + j] + b_hh[1024 + j];
    float i_n   = y[4096 + j] + b_ih[2048 + j];
    float h_n   = y[5120 + j] + b_hh[2048 + j];

    float r = sigmoidf_(pre_r);
    float z = sigmoidf_(pre_z);
    float n = tanhf(i_n + r * h_n);
    float hnew = (1.0f - z) * n + z * h_in[idx];
    h_out[idx] = hnew;
    if (write_a2) {
        __nv_bfloat16 hi = __float2bfloat16(hnew);
        __nv_bfloat16 lo = __float2bfloat16(hnew - __bfloat162float(hi));
        g_A2[(size_t)row * KA + j]        = hi;
        g_A2[(size_t)row * KA + 1024 + j] = lo;
    }
}

// ---------------------------------------------------------------------------
// Launch
// ---------------------------------------------------------------------------
extern "C" void kernel_launch(void* const* d_in, const int* in_sizes, int n_in,
                              void* d_out, int out_size) {
    const float* x      = (const float*)d_in[0];
    const float* w_op1  = (const float*)d_in[2];
    const float* b_op1  = (const float*)d_in[3];
    const float* w_op2  = (const float*)d_in[4];
    const float* b_op2  = (const float*)d_in[5];
    const float* w_num1 = (const float*)d_in[6];
    const float* b_num1 = (const float*)d_in[7];
    const float* w_num2 = (const float*)d_in[8];
    const float* b_num2 = (const float*)d_in[9];
    const float* w_ih   = (const float*)d_in[10];
    const float* b_ih   = (const float*)d_in[11];
    const float* w_hh   = (const float*)d_in[12];
    const float* b_hh   = (const float*)d_in[13];

    float* out = (float*)d_out;
    float* final_state = out;
    float* ops    = out + (size_t)Bb * Hh;
    float* nums   = ops + (size_t)Ss * Bb * 5;
    float* states = nums + (size_t)Ss * Bb;

    static bool attr_set = false;
    if (!attr_set) {
        cudaFuncSetAttribute(gemm_mma, cudaFuncAttributeMaxDynamicSharedMemorySize, SMEM_TOT);
        attr_set = true;
    }

    pack_w2<<<(NW * 1024) / 256, 256>>>(w_op1, w_num1, w_ih, w_hh);
    pack_hw<<<20, 256>>>(w_op2);
    convert_x<<<(Bb * Hh) / 256, 256>>>(x, states);

    for (int s = 0; s < Ss; s++) {
        dim3 ggrid(NW / BN, Bb / BM);   // (24, 128)
        gemm_mma<<<ggrid, 256, SMEM_TOT>>>();

        heads_kernel<<<Bb, 256>>>(b_op1, b_num1, b_op2, w_num2, b_num2,
                                  ops + (size_t)s * Bb * 5, nums + (size_t)s * Bb);

        const float* h = states + (size_t)s * Bb * Hh;
        float* h_out = (s == Ss - 1) ? final_state
                                     : states + (size_t)(s + 1) * Bb * Hh;
        gru_kernel<<<(Bb * Hh) / 256, 256>>>(h, b_ih, b_hh, h_out, (s == Ss - 1) ? 0 : 1);
    }
}

// round 7
// speedup vs baseline: 4.3423x; 1.4484x over previous
#include <cuda_runtime.h>
#include <cuda_fp16.h>
#include <cstdint>
#include <cstddef>

// Problem constants
#define Hh   1024
#define Bb   16384
#define Ss   8
#define NW   6144          // fused GEMM width: [op1 | num1 | rz_r | rz_z | i_n | h_n]
#define KTOT 2048          // split-K: [A*Whi | A*Wlo], A fp16 reused across halves
#define KA   1024          // physical A cols (fp16)
#define NCHUNK 32          // KTOT / 64

#define BM 128
#define BN 256
#define STAGES      4
#define STAGE_BYTES 49152  // A 128x64 fp16 (16KB) + B 256x64 fp16 (32KB)
#define SMEM_TOT    (STAGES * STAGE_BYTES)

// ---------------------------------------------------------------------------
// Device scratch
// ---------------------------------------------------------------------------
__device__ float   g_Y[(size_t)Bb * NW];      // 384 MB GEMM out per step
__device__ __half  g_W2[(size_t)NW * KTOT];   // 25 MB packed split weights [Whi|Wlo]
__device__ __half  g_A2[(size_t)Bb * KA];     // 32 MB fp16 activations
__device__ float   g_Wop2t[5 * Hh];           // transposed op head weights

// ---------------------------------------------------------------------------
// Helpers
// ---------------------------------------------------------------------------
__device__ __forceinline__ float gelu_exact(float x) {
    return 0.5f * x * (1.0f + erff(x * 0.70710678118654752f));
}
__device__ __forceinline__ float sigmoidf_(float x) {
    return 1.0f / (1.0f + expf(-x));
}
__device__ __forceinline__ uint32_t smem_u32(const void* p) {
    uint32_t a;
    asm("{ .reg .u64 t; cvta.to.shared.u64 t, %1; cvt.u32.u64 %0, t; }" : "=r"(a) : "l"(p));
    return a;
}
__device__ __forceinline__ void cpasync16(uint32_t dst, const void* src) {
    asm volatile("cp.async.cg.shared.global [%0], [%1], 16;" :: "r"(dst), "l"(src) : "memory");
}
__device__ __forceinline__ void cp_commit() {
    asm volatile("cp.async.commit_group;" ::: "memory");
}
template <int N>
__device__ __forceinline__ void cp_wait() {
    asm volatile("cp.async.wait_group %0;" :: "n"(N) : "memory");
}
__device__ __forceinline__ void ldsm4(uint32_t* r, uint32_t addr) {
    asm volatile("ldmatrix.sync.aligned.m8n8.x4.shared.b16 {%0,%1,%2,%3}, [%4];"
                 : "=r"(r[0]), "=r"(r[1]), "=r"(r[2]), "=r"(r[3]) : "r"(addr));
}
__device__ __forceinline__ void mma_f16(float* c, const uint32_t* a, const uint32_t* b) {
    asm volatile(
        "mma.sync.aligned.m16n8k16.row.col.f32.f16.f16.f32 "
        "{%0,%1,%2,%3}, {%4,%5,%6,%7}, {%8,%9}, {%0,%1,%2,%3};"
        : "+f"(c[0]), "+f"(c[1]), "+f"(c[2]), "+f"(c[3])
        : "r"(a[0]), "r"(a[1]), "r"(a[2]), "r"(a[3]), "r"(b[0]), "r"(b[1]));
}
__device__ __forceinline__ uint32_t sw128(uint32_t off) {
    return off ^ ((off >> 3) & 0x70);
}

// ---------------------------------------------------------------------------
// Pack split weights g_W2[n][k]: k slots [Whi | Wlo] (fp16 hi/lo of fp32 W)
// ---------------------------------------------------------------------------
__global__ void pack_w2(const float* __restrict__ w_op1, const float* __restrict__ w_num1,
                        const float* __restrict__ w_ih, const float* __restrict__ w_hh) {
    size_t idx = (size_t)blockIdx.x * 256 + threadIdx.x;   // over NW*1024
    int n = (int)(idx >> 10);
    int kk = (int)(idx & 1023);
    int m = n & 1023;
    float v;
    if (n < 1024)      v = w_op1[(size_t)kk * Hh + m];
    else if (n < 2048) v = w_num1[(size_t)kk * Hh + m];
    else if (n < 3072) v = w_ih[(size_t)m * Hh + kk] + w_hh[(size_t)m * Hh + kk];
    else if (n < 4096) v = w_ih[(size_t)(1024 + m) * Hh + kk] + w_hh[(size_t)(1024 + m) * Hh + kk];
    else if (n < 5120) v = w_ih[(size_t)(2048 + m) * Hh + kk];
    else               v = w_hh[(size_t)(2048 + m) * Hh + kk];
    __half hi = __float2half_rn(v);
    __half lo = __float2half_rn(v - __half2float(hi));
    size_t base = (size_t)n * KTOT;
    g_W2[base + kk]        = hi;
    g_W2[base + 1024 + kk] = lo;
}

// transpose w_op2 [H,5] -> g_Wop2t [5,H]
__global__ void pack_hw(const float* __restrict__ w_op2) {
    int idx = blockIdx.x * 256 + threadIdx.x;   // 0..5119
    int q = idx >> 10, c = idx & 1023;
    g_Wop2t[idx] = w_op2[(size_t)c * 5 + q];
}

// states[0] = x, and x -> g_A2 (fp16)
__global__ void convert_x(const float* __restrict__ x, float* __restrict__ states0) {
    size_t idx = (size_t)blockIdx.x * 256 + threadIdx.x;
    float h = x[idx];
    states0[idx] = h;
    g_A2[idx] = __float2half_rn(h);
}

// ---------------------------------------------------------------------------
// HMMA GEMM: Y[m][n] = sum_k A2[m][k] * W2[n][k]  (fp16 in, fp32 accum/out)
// BM=128, BN=256, BK=64. 256 threads = 8 warps (2 m x 4 n), warp tile 64x64.
// 4-stage cp.async pipeline, wait_group<2>, one __syncthreads per chunk.
// A chunk c uses A cols (c & 15)*64.., B uses cols c*64.. ([Whi|Wlo]).
// ---------------------------------------------------------------------------
__global__ void __launch_bounds__(256, 1) gemm_mma() {
    extern __shared__ char smem[];
    uint32_t sb = smem_u32(smem);
    int tid = threadIdx.x;
    int lane = tid & 31;
    int wid = tid >> 5;
    int n0 = blockIdx.x * BN;
    int m0 = blockIdx.y * BM;

    // ---- cp.async bases (strided across i) ----
    int lrow = tid >> 3;            // 0..31
    int ls8 = tid & 7;
    uint32_t d0 = sw128((uint32_t)lrow * 128 + ls8 * 16);
    const char* pA0 = (const char*)(g_A2 + (size_t)(m0 + lrow) * KA) + ls8 * 16;
    const char* pB0 = (const char*)(g_W2 + (size_t)(n0 + lrow) * KTOT) + ls8 * 16;

    // ---- ldmatrix base offsets (ks=0); sw(off + ks*32) == sw(off) ^ (ks*32) ----
    int wm = (wid >> 2) * 64;       // 0 or 64
    int wn = (wid & 3) * 64;        // 0,64,128,192
    uint32_t aoffb[4], boffb[4];
#pragma unroll
    for (int mi = 0; mi < 4; mi++)
        aoffb[mi] = sw128((uint32_t)(wm + mi * 16 + (lane & 15)) * 128 + ((lane >> 4) << 4));
#pragma unroll
    for (int nb = 0; nb < 4; nb++) {
        uint32_t rown = wn + nb * 16 + ((lane >> 4) & 1) * 8 + (lane & 7);
        boffb[nb] = sw128(rown * 128 + ((lane >> 3) & 1) * 16);
    }

    float cc[4][8][4];
#pragma unroll
    for (int mi = 0; mi < 4; mi++)
#pragma unroll
        for (int ni = 0; ni < 8; ni++)
#pragma unroll
            for (int q = 0; q < 4; q++) cc[mi][ni][q] = 0.0f;

    auto load_stage = [&](int st, int c) {
        uint32_t stb = sb + st * STAGE_BYTES;
        int akb = (c & 15) * 128;   // A byte offset (A reused for both W halves)
        int wkb = c * 128;          // B byte offset
#pragma unroll
        for (int i = 0; i < 4; i++)
            cpasync16(stb + d0 + 4096 * i, pA0 + (size_t)i * 32 * (KA * 2) + akb);
#pragma unroll
        for (int i = 0; i < 8; i++)
            cpasync16(stb + 16384 + d0 + 4096 * i, pB0 + (size_t)i * 32 * (KTOT * 2) + wkb);
    };

    // ---- prologue: 3 stages in flight ----
    load_stage(0, 0);
    cp_commit();
    load_stage(1, 1);
    cp_commit();
    load_stage(2, 2);
    cp_commit();

    // ---- main loop: one barrier per chunk ----
    for (int c = 0; c < NCHUNK; c++) {
        cp_wait<2>();
        __syncthreads();
        if (c + 3 < NCHUNK) load_stage((c + 3) & 3, c + 3);
        cp_commit();

        uint32_t stb = sb + (c & 3) * STAGE_BYTES;
#pragma unroll
        for (int ks = 0; ks < 4; ks++) {
            uint32_t kx = (uint32_t)ks * 32;
            uint32_t a[4][4];
#pragma unroll
            for (int mi = 0; mi < 4; mi++) ldsm4(a[mi], stb + (aoffb[mi] ^ kx));
            uint32_t b[8][2];
#pragma unroll
            for (int nb = 0; nb < 4; nb++) {
                uint32_t r[4];
                ldsm4(r, stb + 16384 + (boffb[nb] ^ kx));
                b[nb * 2][0] = r[0]; b[nb * 2][1] = r[1];
                b[nb * 2 + 1][0] = r[2]; b[nb * 2 + 1][1] = r[3];
            }
#pragma unroll
            for (int mi = 0; mi < 4; mi++)
#pragma unroll
                for (int ni = 0; ni < 8; ni++)
                    mma_f16(cc[mi][ni], a[mi], b[ni]);
        }
    }

    // ---- epilogue: registers -> g_Y (fp32) ----
    int mrow = m0 + wm + (lane >> 2);
    int ncol = n0 + wn + (lane & 3) * 2;
#pragma unroll
    for (int mi = 0; mi < 4; mi++) {
#pragma unroll
        for (int ni = 0; ni < 8; ni++) {
            float2 v0 = make_float2(cc[mi][ni][0], cc[mi][ni][1]);
            float2 v1 = make_float2(cc[mi][ni][2], cc[mi][ni][3]);
            *(float2*)&g_Y[(size_t)(mrow + mi * 16) * NW + ncol + ni * 8] = v0;
            *(float2*)&g_Y[(size_t)(mrow + mi * 16 + 8) * NW + ncol + ni * 8] = v1;
        }
    }
}

// ---------------------------------------------------------------------------
// Fused epilogue: heads (GELU + tiny matmuls) + GRU combine, one block per row.
// ---------------------------------------------------------------------------
__global__ __launch_bounds__(256)
void fused_epi(const float* __restrict__ b_op1, const float* __restrict__ b_num1,
               const float* __restrict__ b_op2,
               const float* __restrict__ w_num2, const float* __restrict__ b_num2,
               const float* __restrict__ b_ih, const float* __restrict__ b_hh,
               const float* __restrict__ h_in,
               float* __restrict__ ops_out, float* __restrict__ nums_out,
               float* __restrict__ h_out, int write_a2) {
    int row = blockIdx.x;
    int t = threadIdx.x;
    const float* y = g_Y + (size_t)row * NW;

    // ---- heads ----
    float acc[5] = {0.f, 0.f, 0.f, 0.f, 0.f};
    float accn = 0.f;
#pragma unroll
    for (int it = 0; it < Hh / 256; it++) {
        int c = t + it * 256;
        float a = gelu_exact(y[c] + b_op1[c]);
#pragma unroll
        for (int q = 0; q < 5; q++) acc[q] += a * g_Wop2t[q * Hh + c];
        float an = gelu_exact(y[Hh + c] + b_num1[c]);
        accn += an * w_num2[c];
    }
#pragma unroll
    for (int off = 16; off > 0; off >>= 1) {
#pragma unroll
        for (int q = 0; q < 5; q++) acc[q] += __shfl_down_sync(0xffffffffu, acc[q], off);
        accn += __shfl_down_sync(0xffffffffu, accn, off);
    }
    __shared__ float red[8][6];
    int warp = t >> 5, lane = t & 31;
    if (lane == 0) {
#pragma unroll
        for (int q = 0; q < 5; q++) red[warp][q] = acc[q];
        red[warp][5] = accn;
    }
    __syncthreads();
    if (t < 6) {
        float s = 0.f;
#pragma unroll
        for (int w = 0; w < 8; w++) s += red[w][t];
        if (t < 5) ops_out[(size_t)row * 5 + t] = s + b_op2[t];
        else       nums_out[row] = s + b_num2[0];
    }

    // ---- GRU combine (4 elements per thread) ----
#pragma unroll
    for (int it = 0; it < Hh / 256; it++) {
        int j = t + it * 256;
        float pre_r = y[2048 + j] + b_ih[j] + b_hh[j];
        float pre_z = y[3072 + j] + b_ih[1024 + j] + b_hh[1024 + j];
        float i_n   = y[4096 + j] + b_ih[2048 + j];
        float h_n   = y[5120 + j] + b_hh[2048 + j];
        float r = sigmoidf_(pre_r);
        float z = sigmoidf_(pre_z);
        float n = tanhf(i_n + r * h_n);
        size_t idx = (size_t)row * Hh + j;
        float hnew = (1.0f - z) * n + z * h_in[idx];
        h_out[idx] = hnew;
        if (write_a2) g_A2[idx] = __float2half_rn(hnew);
    }
}

// ---------------------------------------------------------------------------
// Launch
// ---------------------------------------------------------------------------
extern "C" void kernel_launch(void* const* d_in, const int* in_sizes, int n_in,
                              void* d_out, int out_size) {
    const float* x      = (const float*)d_in[0];
    const float* w_op1  = (const float*)d_in[2];
    const float* b_op1  = (const float*)d_in[3];
    const float* w_op2  = (const float*)d_in[4];
    const float* b_op2  = (const float*)d_in[5];
    const float* w_num1 = (const float*)d_in[6];
    const float* b_num1 = (const float*)d_in[7];
    const float* w_num2 = (const float*)d_in[8];
    const float* b_num2 = (const float*)d_in[9];
    const float* w_ih   = (const float*)d_in[10];
    const float* b_ih   = (const float*)d_in[11];
    const float* w_hh   = (const float*)d_in[12];
    const float* b_hh   = (const float*)d_in[13];

    float* out = (float*)d_out;
    float* final_state = out;
    float* ops    = out + (size_t)Bb * Hh;
    float* nums   = ops + (size_t)Ss * Bb * 5;
    float* states = nums + (size_t)Ss * Bb;

    static bool attr_set = false;
    if (!attr_set) {
        cudaFuncSetAttribute(gemm_mma, cudaFuncAttributeMaxDynamicSharedMemorySize, SMEM_TOT);
        attr_set = true;
    }

    pack_w2<<<(NW * 1024) / 256, 256>>>(w_op1, w_num1, w_ih, w_hh);
    pack_hw<<<20, 256>>>(w_op2);
    convert_x<<<(Bb * Hh) / 256, 256>>>(x, states);

    for (int s = 0; s < Ss; s++) {
        dim3 ggrid(NW / BN, Bb / BM);   // (24, 128)
        gemm_mma<<<ggrid, 256, SMEM_TOT>>>();

        const float* h = states + (size_t)s * Bb * Hh;
        float* h_out = (s == Ss - 1) ? final_state
                                     : states + (size_t)(s + 1) * Bb * Hh;
        fused_epi<<<Bb, 256>>>(b_op1, b_num1, b_op2, w_num2, b_num2,
                               b_ih, b_hh, h,
                               ops + (size_t)s * Bb * 5, nums + (size_t)s * Bb,
                               h_out, (s == Ss - 1) ? 0 : 1);
    }
}

// round 8
// speedup vs baseline: 5.1291x; 1.1812x over previous
#include <cuda_runtime.h>
#include <cuda_fp16.h>
#include <cstdint>
#include <cstddef>

// Problem constants
#define Hh   1024
#define Bb   16384
#define Ss   8
#define NW   6144          // fused GEMM width: [op1 | num1 | rz_r | rz_z | i_n | h_n]
#define KTOT 1024          // single fp16 pass
#define NCHUNK 16          // KTOT / 64

#define BM 128
#define BN 256
#define STAGES      4
#define STAGE_BYTES 49152  // A 128x64 fp16 (16KB) + B 256x64 fp16 (32KB)
#define SMEM_TOT    (STAGES * STAGE_BYTES)
#define NTHREADS    512

// ---------------------------------------------------------------------------
// Device scratch
// ---------------------------------------------------------------------------
__device__ float   g_Y[(size_t)Bb * NW];      // 384 MB GEMM out per step
__device__ __half  g_W2[(size_t)NW * KTOT];   // 12.6 MB packed fp16 weights
__device__ __half  g_A2[(size_t)Bb * KTOT];   // 32 MB fp16 activations
__device__ float   g_Wop2t[5 * Hh];           // transposed op head weights

// ---------------------------------------------------------------------------
// Helpers
// ---------------------------------------------------------------------------
__device__ __forceinline__ float gelu_exact(float x) {
    return 0.5f * x * (1.0f + erff(x * 0.70710678118654752f));
}
__device__ __forceinline__ float sigmoidf_(float x) {
    return 1.0f / (1.0f + expf(-x));
}
__device__ __forceinline__ uint32_t smem_u32(const void* p) {
    uint32_t a;
    asm("{ .reg .u64 t; cvta.to.shared.u64 t, %1; cvt.u32.u64 %0, t; }" : "=r"(a) : "l"(p));
    return a;
}
__device__ __forceinline__ void cpasync16(uint32_t dst, const void* src) {
    asm volatile("cp.async.cg.shared.global [%0], [%1], 16;" :: "r"(dst), "l"(src) : "memory");
}
__device__ __forceinline__ void cp_commit() {
    asm volatile("cp.async.commit_group;" ::: "memory");
}
template <int N>
__device__ __forceinline__ void cp_wait() {
    asm volatile("cp.async.wait_group %0;" :: "n"(N) : "memory");
}
__device__ __forceinline__ void ldsm4(uint32_t* r, uint32_t addr) {
    asm volatile("ldmatrix.sync.aligned.m8n8.x4.shared.b16 {%0,%1,%2,%3}, [%4];"
                 : "=r"(r[0]), "=r"(r[1]), "=r"(r[2]), "=r"(r[3]) : "r"(addr));
}
__device__ __forceinline__ void mma_f16(float* c, const uint32_t* a, const uint32_t* b) {
    asm volatile(
        "mma.sync.aligned.m16n8k16.row.col.f32.f16.f16.f32 "
        "{%0,%1,%2,%3}, {%4,%5,%6,%7}, {%8,%9}, {%0,%1,%2,%3};"
        : "+f"(c[0]), "+f"(c[1]), "+f"(c[2]), "+f"(c[3])
        : "r"(a[0]), "r"(a[1]), "r"(a[2]), "r"(a[3]), "r"(b[0]), "r"(b[1]));
}
__device__ __forceinline__ uint32_t sw128(uint32_t off) {
    return off ^ ((off >> 3) & 0x70);
}

// ---------------------------------------------------------------------------
// Pack fp16 weights g_W2[n][k]
// ---------------------------------------------------------------------------
__global__ void pack_w2(const float* __restrict__ w_op1, const float* __restrict__ w_num1,
                        const float* __restrict__ w_ih, const float* __restrict__ w_hh) {
    size_t idx = (size_t)blockIdx.x * 256 + threadIdx.x;   // over NW*1024
    int n = (int)(idx >> 10);
    int kk = (int)(idx & 1023);
    int m = n & 1023;
    float v;
    if (n < 1024)      v = w_op1[(size_t)kk * Hh + m];
    else if (n < 2048) v = w_num1[(size_t)kk * Hh + m];
    else if (n < 3072) v = w_ih[(size_t)m * Hh + kk] + w_hh[(size_t)m * Hh + kk];
    else if (n < 4096) v = w_ih[(size_t)(1024 + m) * Hh + kk] + w_hh[(size_t)(1024 + m) * Hh + kk];
    else if (n < 5120) v = w_ih[(size_t)(2048 + m) * Hh + kk];
    else               v = w_hh[(size_t)(2048 + m) * Hh + kk];
    g_W2[idx] = __float2half_rn(v);
}

// transpose w_op2 [H,5] -> g_Wop2t [5,H]
__global__ void pack_hw(const float* __restrict__ w_op2) {
    int idx = blockIdx.x * 256 + threadIdx.x;   // 0..5119
    int q = idx >> 10, c = idx & 1023;
    g_Wop2t[idx] = w_op2[(size_t)c * 5 + q];
}

// states[0] = x, and x -> g_A2 (fp16)
__global__ void convert_x(const float* __restrict__ x, float* __restrict__ states0) {
    size_t idx = (size_t)blockIdx.x * 256 + threadIdx.x;
    float h = x[idx];
    states0[idx] = h;
    g_A2[idx] = __float2half_rn(h);
}

// ---------------------------------------------------------------------------
// HMMA GEMM: Y[m][n] = sum_k A2[m][k] * W2[n][k]  (fp16 in, fp32 accum/out)
// BM=128, BN=256, BK=64. 512 threads = 16 warps (2 m x 8 n), warp tile 64x32.
// 4-stage cp.async pipeline, wait_group<2>, one __syncthreads per chunk.
// ---------------------------------------------------------------------------
__global__ void __launch_bounds__(NTHREADS, 1) gemm_mma() {
    extern __shared__ char smem[];
    uint32_t sb = smem_u32(smem);
    int tid = threadIdx.x;
    int lane = tid & 31;
    int wid = tid >> 5;
    int n0 = blockIdx.x * BN;
    int m0 = blockIdx.y * BM;

    // ---- cp.async bases: 6 segs/thread (2 A + 4 B), strided by 64 rows ----
    int lrow = tid >> 3;            // 0..63
    int ls8 = tid & 7;
    uint32_t d0 = sw128((uint32_t)lrow * 128 + ls8 * 16);
    const char* pA0 = (const char*)(g_A2 + (size_t)(m0 + lrow) * KTOT) + ls8 * 16;
    const char* pB0 = (const char*)(g_W2 + (size_t)(n0 + lrow) * KTOT) + ls8 * 16;

    // ---- ldmatrix base offsets (ks=0); sw(off ^ ks*32) ----
    int wm = (wid >> 3) * 64;       // 0 or 64
    int wn = (wid & 7) * 32;        // 0..224
    uint32_t aoffb[4], boffb[2];
#pragma unroll
    for (int mi = 0; mi < 4; mi++)
        aoffb[mi] = sw128((uint32_t)(wm + mi * 16 + (lane & 15)) * 128 + ((lane >> 4) << 4));
#pragma unroll
    for (int nb = 0; nb < 2; nb++) {
        uint32_t rown = wn + nb * 16 + ((lane >> 4) & 1) * 8 + (lane & 7);
        boffb[nb] = sw128(rown * 128 + ((lane >> 3) & 1) * 16);
    }

    float cc[4][4][4];
#pragma unroll
    for (int mi = 0; mi < 4; mi++)
#pragma unroll
        for (int ni = 0; ni < 4; ni++)
#pragma unroll
            for (int q = 0; q < 4; q++) cc[mi][ni][q] = 0.0f;

    auto load_stage = [&](int st, int c) {
        uint32_t stb = sb + st * STAGE_BYTES;
        int kb = c * 128;
#pragma unroll
        for (int i = 0; i < 2; i++)
            cpasync16(stb + d0 + 8192 * i, pA0 + (size_t)i * 64 * (KTOT * 2) + kb);
#pragma unroll
        for (int i = 0; i < 4; i++)
            cpasync16(stb + 16384 + d0 + 8192 * i, pB0 + (size_t)i * 64 * (KTOT * 2) + kb);
    };

    // ---- prologue: 3 stages in flight ----
    load_stage(0, 0);
    cp_commit();
    load_stage(1, 1);
    cp_commit();
    load_stage(2, 2);
    cp_commit();

    // ---- main loop: one barrier per chunk ----
    for (int c = 0; c < NCHUNK; c++) {
        cp_wait<2>();
        __syncthreads();
        if (c + 3 < NCHUNK) load_stage((c + 3) & 3, c + 3);
        cp_commit();

        uint32_t stb = sb + (c & 3) * STAGE_BYTES;
#pragma unroll
        for (int ks = 0; ks < 4; ks++) {
            uint32_t kx = (uint32_t)ks * 32;
            uint32_t a[4][4];
#pragma unroll
            for (int mi = 0; mi < 4; mi++) ldsm4(a[mi], stb + (aoffb[mi] ^ kx));
            uint32_t b[4][2];
#pragma unroll
            for (int nb = 0; nb < 2; nb++) {
                uint32_t r[4];
                ldsm4(r, stb + 16384 + (boffb[nb] ^ kx));
                b[nb * 2][0] = r[0]; b[nb * 2][1] = r[1];
                b[nb * 2 + 1][0] = r[2]; b[nb * 2 + 1][1] = r[3];
            }
#pragma unroll
            for (int mi = 0; mi < 4; mi++)
#pragma unroll
                for (int ni = 0; ni < 4; ni++)
                    mma_f16(cc[mi][ni], a[mi], b[ni]);
        }
    }

    // ---- epilogue: registers -> g_Y (fp32) ----
    int mrow = m0 + wm + (lane >> 2);
    int ncol = n0 + wn + (lane & 3) * 2;
#pragma unroll
    for (int mi = 0; mi < 4; mi++) {
#pragma unroll
        for (int ni = 0; ni < 4; ni++) {
            float2 v0 = make_float2(cc[mi][ni][0], cc[mi][ni][1]);
            float2 v1 = make_float2(cc[mi][ni][2], cc[mi][ni][3]);
            *(float2*)&g_Y[(size_t)(mrow + mi * 16) * NW + ncol + ni * 8] = v0;
            *(float2*)&g_Y[(size_t)(mrow + mi * 16 + 8) * NW + ncol + ni * 8] = v1;
        }
    }
}

// ---------------------------------------------------------------------------
// Fused epilogue: heads (GELU + tiny matmuls) + GRU combine, one block per row.
// ---------------------------------------------------------------------------
__global__ __launch_bounds__(256)
void fused_epi(const float* __restrict__ b_op1, const float* __restrict__ b_num1,
               const float* __restrict__ b_op2,
               const float* __restrict__ w_num2, const float* __restrict__ b_num2,
               const float* __restrict__ b_ih, const float* __restrict__ b_hh,
               const float* __restrict__ h_in,
               float* __restrict__ ops_out, float* __restrict__ nums_out,
               float* __restrict__ h_out, int write_a2) {
    int row = blockIdx.x;
    int t = threadIdx.x;
    const float* y = g_Y + (size_t)row * NW;

    // ---- heads ----
    float acc[5] = {0.f, 0.f, 0.f, 0.f, 0.f};
    float accn = 0.f;
#pragma unroll
    for (int it = 0; it < Hh / 256; it++) {
        int c = t + it * 256;
        float a = gelu_exact(y[c] + b_op1[c]);
#pragma unroll
        for (int q = 0; q < 5; q++) acc[q] += a * g_Wop2t[q * Hh + c];
        float an = gelu_exact(y[Hh + c] + b_num1[c]);
        accn += an * w_num2[c];
    }
#pragma unroll
    for (int off = 16; off > 0; off >>= 1) {
#pragma unroll
        for (int q = 0; q < 5; q++) acc[q] += __shfl_down_sync(0xffffffffu, acc[q], off);
        accn += __shfl_down_sync(0xffffffffu, accn, off);
    }
    __shared__ float red[8][6];
    int warp = t >> 5, lane = t & 31;
    if (lane == 0) {
#pragma unroll
        for (int q = 0; q < 5; q++) red[warp][q] = acc[q];
        red[warp][5] = accn;
    }
    __syncthreads();
    if (t < 6) {
        float s = 0.f;
#pragma unroll
        for (int w = 0; w < 8; w++) s += red[w][t];
        if (t < 5) ops_out[(size_t)row * 5 + t] = s + b_op2[t];
        else       nums_out[row] = s + b_num2[0];
    }

    // ---- GRU combine (4 elements per thread) ----
#pragma unroll
    for (int it = 0; it < Hh / 256; it++) {
        int j = t + it * 256;
        float pre_r = y[2048 + j] + b_ih[j] + b_hh[j];
        float pre_z = y[3072 + j] + b_ih[1024 + j] + b_hh[1024 + j];
        float i_n   = y[4096 + j] + b_ih[2048 + j];
        float h_n   = y[5120 + j] + b_hh[2048 + j];
        float r = sigmoidf_(pre_r);
        float z = sigmoidf_(pre_z);
        float n = tanhf(i_n + r * h_n);
        size_t idx = (size_t)row * Hh + j;
        float hnew = (1.0f - z) * n + z * h_in[idx];
        h_out[idx] = hnew;
        if (write_a2) g_A2[idx] = __float2half_rn(hnew);
    }
}

// ---------------------------------------------------------------------------
// Launch
// ---------------------------------------------------------------------------
extern "C" void kernel_launch(void* const* d_in, const int* in_sizes, int n_in,
                              void* d_out, int out_size) {
    const float* x      = (const float*)d_in[0];
    const float* w_op1  = (const float*)d_in[2];
    const float* b_op1  = (const float*)d_in[3];
    const float* w_op2  = (const float*)d_in[4];
    const float* b_op2  = (const float*)d_in[5];
    const float* w_num1 = (const float*)d_in[6];
    const float* b_num1 = (const float*)d_in[7];
    const float* w_num2 = (const float*)d_in[8];
    const float* b_num2 = (const float*)d_in[9];
    const float* w_ih   = (const float*)d_in[10];
    const float* b_ih   = (const float*)d_in[11];
    const float* w_hh   = (const float*)d_in[12];
    const float* b_hh   = (const float*)d_in[13];

    float* out = (float*)d_out;
    float* final_state = out;
    float* ops    = out + (size_t)Bb * Hh;
    float* nums   = ops + (size_t)Ss * Bb * 5;
    float* states = nums + (size_t)Ss * Bb;

    static bool attr_set = false;
    if (!attr_set) {
        cudaFuncSetAttribute(gemm_mma, cudaFuncAttributeMaxDynamicSharedMemorySize, SMEM_TOT);
        attr_set = true;
    }

    pack_w2<<<(NW * 1024) / 256, 256>>>(w_op1, w_num1, w_ih, w_hh);
    pack_hw<<<20, 256>>>(w_op2);
    convert_x<<<(Bb * Hh) / 256, 256>>>(x, states);

    for (int s = 0; s < Ss; s++) {
        dim3 ggrid(NW / BN, Bb / BM);   // (24, 128)
        gemm_mma<<<ggrid, NTHREADS, SMEM_TOT>>>();

        const float* h = states + (size_t)s * Bb * Hh;
        float* h_out = (s == Ss - 1) ? final_state
                                     : states + (size_t)(s + 1) * Bb * Hh;
        fused_epi<<<Bb, 256>>>(b_op1, b_num1, b_op2, w_num2, b_num2,
                               b_ih, b_hh, h,
                               ops + (size_t)s * Bb * 5, nums + (size_t)s * Bb,
                               h_out, (s == Ss - 1) ? 0 : 1);
    }
}

// round 9
// speedup vs baseline: 7.8209x; 1.5248x over previous
#include <cuda_runtime.h>
#include <cuda_fp16.h>
#include <cstdint>
#include <cstddef>

// Problem constants
#define Hh   1024
#define Bb   16384
#define Ss   8
#define NW   6144          // [op1 | num1 | gates interleaved 4*j+g]
#define KTOT 1024
#define NCHUNK 16          // KTOT / 64

#define BM 128
#define BN 256
#define STAGES      4
#define STAGE_BYTES 49152  // A 128x64 fp16 (16KB) + B 256x64 fp16 (32KB)
#define SMEM_TOT    (STAGES * STAGE_BYTES)
#define NTHREADS    512

// ---------------------------------------------------------------------------
// Device scratch
// ---------------------------------------------------------------------------
__device__ __half  g_W2[(size_t)NW * KTOT];      // 12.6 MB packed fp16 weights
__device__ __half  g_A2[2][(size_t)Bb * KTOT];   // ping-pong fp16 activations
__device__ float   g_Wop2t[5 * Hh];              // transposed op head weights
__device__ float   g_hb[2 * Hh];                 // [b_op1 | b_num1]
__device__ float   g_gb[4 * Hh];                 // interleaved gate biases

// ---------------------------------------------------------------------------
// Helpers
// ---------------------------------------------------------------------------
__device__ __forceinline__ float gelu_exact(float x) {
    return 0.5f * x * (1.0f + erff(x * 0.70710678118654752f));
}
__device__ __forceinline__ float fast_sig(float x) {
    return __fdividef(1.0f, 1.0f + __expf(-x));
}
__device__ __forceinline__ float fast_tanh(float x) {
    return __fdividef(2.0f, 1.0f + __expf(-2.0f * x)) - 1.0f;
}
__device__ __forceinline__ uint32_t smem_u32(const void* p) {
    uint32_t a;
    asm("{ .reg .u64 t; cvta.to.shared.u64 t, %1; cvt.u32.u64 %0, t; }" : "=r"(a) : "l"(p));
    return a;
}
__device__ __forceinline__ void cpasync16(uint32_t dst, const void* src) {
    asm volatile("cp.async.cg.shared.global [%0], [%1], 16;" :: "r"(dst), "l"(src) : "memory");
}
__device__ __forceinline__ void cp_commit() {
    asm volatile("cp.async.commit_group;" ::: "memory");
}
template <int N>
__device__ __forceinline__ void cp_wait() {
    asm volatile("cp.async.wait_group %0;" :: "n"(N) : "memory");
}
__device__ __forceinline__ void ldsm4(uint32_t* r, uint32_t addr) {
    asm volatile("ldmatrix.sync.aligned.m8n8.x4.shared.b16 {%0,%1,%2,%3}, [%4];"
                 : "=r"(r[0]), "=r"(r[1]), "=r"(r[2]), "=r"(r[3]) : "r"(addr));
}
__device__ __forceinline__ void mma_f16(float* c, const uint32_t* a, const uint32_t* b) {
    asm volatile(
        "mma.sync.aligned.m16n8k16.row.col.f32.f16.f16.f32 "
        "{%0,%1,%2,%3}, {%4,%5,%6,%7}, {%8,%9}, {%0,%1,%2,%3};"
        : "+f"(c[0]), "+f"(c[1]), "+f"(c[2]), "+f"(c[3])
        : "r"(a[0]), "r"(a[1]), "r"(a[2]), "r"(a[3]), "r"(b[0]), "r"(b[1]));
}
__device__ __forceinline__ uint32_t sw128(uint32_t off) {
    return off ^ ((off >> 3) & 0x70);
}

// ---------------------------------------------------------------------------
// Pack fp16 weights, gate-interleaved:
//   n<1024: op1^T; n<2048: num1^T;
//   n>=2048: j=(n-2048)>>2, g=n&3: [r_comb | z_comb | i_n | h_n]
// ---------------------------------------------------------------------------
__global__ void pack_w2(const float* __restrict__ w_op1, const float* __restrict__ w_num1,
                        const float* __restrict__ w_ih, const float* __restrict__ w_hh) {
    size_t idx = (size_t)blockIdx.x * 256 + threadIdx.x;   // over NW*1024
    int n = (int)(idx >> 10);
    int kk = (int)(idx & 1023);
    float v;
    if (n < 1024)      v = w_op1[(size_t)kk * Hh + n];
    else if (n < 2048) v = w_num1[(size_t)kk * Hh + (n - 1024)];
    else {
        int j = (n - 2048) >> 2;
        int g = n & 3;
        if (g == 0)      v = w_ih[(size_t)j * Hh + kk] + w_hh[(size_t)j * Hh + kk];
        else if (g == 1) v = w_ih[(size_t)(1024 + j) * Hh + kk] + w_hh[(size_t)(1024 + j) * Hh + kk];
        else if (g == 2) v = w_ih[(size_t)(2048 + j) * Hh + kk];
        else             v = w_hh[(size_t)(2048 + j) * Hh + kk];
    }
    g_W2[idx] = __float2half_rn(v);
}

// pack w_op2^T, head biases, interleaved gate biases
__global__ void pack_misc(const float* __restrict__ w_op2,
                          const float* __restrict__ b_op1, const float* __restrict__ b_num1,
                          const float* __restrict__ b_ih, const float* __restrict__ b_hh) {
    int idx = blockIdx.x * 256 + threadIdx.x;   // 0..11263
    if (idx < 5120) {
        int q = idx >> 10, c = idx & 1023;
        g_Wop2t[idx] = w_op2[(size_t)c * 5 + q];
    } else if (idx < 5120 + 2048) {
        int c = idx - 5120;
        g_hb[c] = (c < 1024) ? b_op1[c] : b_num1[c - 1024];
    } else if (idx < 5120 + 2048 + 4096) {
        int c = idx - 5120 - 2048;
        int j = c >> 2, g = c & 3;
        float v;
        if (g == 0)      v = b_ih[j] + b_hh[j];
        else if (g == 1) v = b_ih[1024 + j] + b_hh[1024 + j];
        else if (g == 2) v = b_ih[2048 + j];
        else             v = b_hh[2048 + j];
        g_gb[c] = v;
    }
}

// states[0] = x, and x -> g_A2[0] (fp16)
__global__ void convert_x(const float* __restrict__ x, float* __restrict__ states0) {
    size_t idx = (size_t)blockIdx.x * 256 + threadIdx.x;
    float h = x[idx];
    states0[idx] = h;
    g_A2[0][idx] = __float2half_rn(h);
}

// per-step: ops = b_op2 (broadcast), nums = b_num2
__global__ void init_heads(float* __restrict__ ops, float* __restrict__ nums,
                           const float* __restrict__ b_op2, const float* __restrict__ b_num2) {
    int idx = blockIdx.x * 256 + threadIdx.x;   // 0..98303
    if (idx < Bb * 5) ops[idx] = b_op2[idx % 5];
    else              nums[idx - Bb * 5] = b_num2[0];
}

// ---------------------------------------------------------------------------
// Fused HMMA GEMM + heads/GRU epilogue.
// BM=128, BN=256, BK=64. 512 threads = 16 warps (2 m x 8 n), warp tile 64x32.
// Head CTAs (blockIdx.x < 8): GELU + w2 partials -> atomicAdd ops/nums.
// Gate CTAs: interleaved 4-gate columns -> GRU combine -> h_out + Aout(fp16).
// ---------------------------------------------------------------------------
__global__ void __launch_bounds__(NTHREADS, 1)
gemm_fused(const __half* __restrict__ Ain, __half* __restrict__ Aout,
           const float* __restrict__ h_in, float* __restrict__ h_out,
           const float* __restrict__ w_num2,
           float* __restrict__ ops, float* __restrict__ nums) {
    extern __shared__ char smem[];
    uint32_t sb = smem_u32(smem);
    int tid = threadIdx.x;
    int lane = tid & 31;
    int wid = tid >> 5;
    int n0 = blockIdx.x * BN;
    int m0 = blockIdx.y * BM;

    // ---- cp.async bases: 6 segs/thread (2 A + 4 B) ----
    int lrow = tid >> 3;            // 0..63
    int ls8 = tid & 7;
    uint32_t d0 = sw128((uint32_t)lrow * 128 + ls8 * 16);
    const char* pA0 = (const char*)(Ain + (size_t)(m0 + lrow) * KTOT) + ls8 * 16;
    const char* pB0 = (const char*)(g_W2 + (size_t)(n0 + lrow) * KTOT) + ls8 * 16;

    // ---- ldmatrix base offsets ----
    int wm = (wid >> 3) * 64;       // 0 or 64
    int wn = (wid & 7) * 32;        // 0..224
    uint32_t aoffb[4], boffb[2];
#pragma unroll
    for (int mi = 0; mi < 4; mi++)
        aoffb[mi] = sw128((uint32_t)(wm + mi * 16 + (lane & 15)) * 128 + ((lane >> 4) << 4));
#pragma unroll
    for (int nb = 0; nb < 2; nb++) {
        uint32_t rown = wn + nb * 16 + ((lane >> 4) & 1) * 8 + (lane & 7);
        boffb[nb] = sw128(rown * 128 + ((lane >> 3) & 1) * 16);
    }

    float cc[4][4][4];
#pragma unroll
    for (int mi = 0; mi < 4; mi++)
#pragma unroll
        for (int ni = 0; ni < 4; ni++)
#pragma unroll
            for (int q = 0; q < 4; q++) cc[mi][ni][q] = 0.0f;

    auto load_stage = [&](int st, int c) {
        uint32_t stb = sb + st * STAGE_BYTES;
        int kb = c * 128;
#pragma unroll
        for (int i = 0; i < 2; i++)
            cpasync16(stb + d0 + 8192 * i, pA0 + (size_t)i * 64 * (KTOT * 2) + kb);
#pragma unroll
        for (int i = 0; i < 4; i++)
            cpasync16(stb + 16384 + d0 + 8192 * i, pB0 + (size_t)i * 64 * (KTOT * 2) + kb);
    };

    load_stage(0, 0);
    cp_commit();
    load_stage(1, 1);
    cp_commit();
    load_stage(2, 2);
    cp_commit();

    for (int c = 0; c < NCHUNK; c++) {
        cp_wait<2>();
        __syncthreads();
        if (c + 3 < NCHUNK) load_stage((c + 3) & 3, c + 3);
        cp_commit();

        uint32_t stb = sb + (c & 3) * STAGE_BYTES;
#pragma unroll
        for (int ks = 0; ks < 4; ks++) {
            uint32_t kx = (uint32_t)ks * 32;
            uint32_t a[4][4];
#pragma unroll
            for (int mi = 0; mi < 4; mi++) ldsm4(a[mi], stb + (aoffb[mi] ^ kx));
            uint32_t b[4][2];
#pragma unroll
            for (int nb = 0; nb < 2; nb++) {
                uint32_t r[4];
                ldsm4(r, stb + 16384 + (boffb[nb] ^ kx));
                b[nb * 2][0] = r[0]; b[nb * 2][1] = r[1];
                b[nb * 2 + 1][0] = r[2]; b[nb * 2 + 1][1] = r[3];
            }
#pragma unroll
            for (int mi = 0; mi < 4; mi++)
#pragma unroll
                for (int ni = 0; ni < 4; ni++)
                    mma_f16(cc[mi][ni], a[mi], b[ni]);
        }
    }

    // ---- fused epilogue ----
    int mrow = m0 + wm + (lane >> 2);
    int cbase = n0 + wn + (lane & 3) * 2;

    if (blockIdx.x >= 8) {
        // ======== gate CTAs: GRU combine ========
        int odd = lane & 1;
#pragma unroll
        for (int ni = 0; ni < 4; ni++) {
            int col = cbase + ni * 8;
            int j = (col - 2048) >> 2;
            float b0 = g_gb[col - 2048];
            float b1 = g_gb[col - 2048 + 1];
#pragma unroll
            for (int mi = 0; mi < 4; mi++) {
#pragma unroll
                for (int hf = 0; hf < 2; hf++) {
                    float v0 = cc[mi][ni][hf * 2 + 0] + b0;
                    float v1 = cc[mi][ni][hf * 2 + 1] + b1;
                    float u0 = __shfl_xor_sync(0xffffffffu, v0, 1);
                    float u1 = __shfl_xor_sync(0xffffffffu, v1, 1);
                    float pre_r = odd ? u0 : v0;
                    float pre_z = odd ? u1 : v1;
                    float i_n   = odd ? v0 : u0;
                    float h_n   = odd ? v1 : u1;
                    float r = fast_sig(pre_r);
                    float z = fast_sig(pre_z);
                    float nn = fast_tanh(fmaf(r, h_n, i_n));
                    int row = mrow + mi * 16 + hf * 8;
                    size_t idx = (size_t)row * Hh + j;
                    float hold = h_in[idx];
                    float hnew = fmaf(z, hold - nn, nn);
                    if (!odd) h_out[idx] = hnew;
                    else      Aout[idx] = __float2half_rn(hnew);
                }
            }
        }
    } else if (n0 < 1024) {
        // ======== op head CTAs: GELU + w_op2 partials ========
        float p[8][5];
#pragma unroll
        for (int ri = 0; ri < 8; ri++)
#pragma unroll
            for (int q = 0; q < 5; q++) p[ri][q] = 0.0f;
#pragma unroll
        for (int ni = 0; ni < 4; ni++) {
            int col = cbase + ni * 8;
            float b0 = g_hb[col], b1 = g_hb[col + 1];
            float w0[5], w1[5];
#pragma unroll
            for (int q = 0; q < 5; q++) {
                w0[q] = g_Wop2t[q * Hh + col];
                w1[q] = g_Wop2t[q * Hh + col + 1];
            }
#pragma unroll
            for (int mi = 0; mi < 4; mi++) {
#pragma unroll
                for (int hf = 0; hf < 2; hf++) {
                    float a0 = gelu_exact(cc[mi][ni][hf * 2 + 0] + b0);
                    float a1 = gelu_exact(cc[mi][ni][hf * 2 + 1] + b1);
                    int ri = mi * 2 + hf;
#pragma unroll
                    for (int q = 0; q < 5; q++)
                        p[ri][q] += a0 * w0[q] + a1 * w1[q];
                }
            }
        }
#pragma unroll
        for (int ri = 0; ri < 8; ri++)
#pragma unroll
            for (int q = 0; q < 5; q++) {
                p[ri][q] += __shfl_xor_sync(0xffffffffu, p[ri][q], 1);
                p[ri][q] += __shfl_xor_sync(0xffffffffu, p[ri][q], 2);
            }
        if ((lane & 3) == 0) {
#pragma unroll
            for (int ri = 0; ri < 8; ri++) {
                int row = mrow + (ri >> 1) * 16 + (ri & 1) * 8;
#pragma unroll
                for (int q = 0; q < 5; q++)
                    atomicAdd(&ops[(size_t)row * 5 + q], p[ri][q]);
            }
        }
    } else {
        // ======== num head CTAs ========
        float pn[8];
#pragma unroll
        for (int ri = 0; ri < 8; ri++) pn[ri] = 0.0f;
#pragma unroll
        for (int ni = 0; ni < 4; ni++) {
            int col = cbase + ni * 8;
            float b0 = g_hb[col], b1 = g_hb[col + 1];
            float w0 = w_num2[col - 1024], w1 = w_num2[col - 1024 + 1];
#pragma unroll
            for (int mi = 0; mi < 4; mi++) {
#pragma unroll
                for (int hf = 0; hf < 2; hf++) {
                    float a0 = gelu_exact(cc[mi][ni][hf * 2 + 0] + b0);
                    float a1 = gelu_exact(cc[mi][ni][hf * 2 + 1] + b1);
                    pn[mi * 2 + hf] += a0 * w0 + a1 * w1;
                }
            }
        }
#pragma unroll
        for (int ri = 0; ri < 8; ri++) {
            pn[ri] += __shfl_xor_sync(0xffffffffu, pn[ri], 1);
            pn[ri] += __shfl_xor_sync(0xffffffffu, pn[ri], 2);
        }
        if ((lane & 3) == 0) {
#pragma unroll
            for (int ri = 0; ri < 8; ri++) {
                int row = mrow + (ri >> 1) * 16 + (ri & 1) * 8;
                atomicAdd(&nums[row], pn[ri]);
            }
        }
    }
}

// ---------------------------------------------------------------------------
// Launch
// ---------------------------------------------------------------------------
extern "C" void kernel_launch(void* const* d_in, const int* in_sizes, int n_in,
                              void* d_out, int out_size) {
    const float* x      = (const float*)d_in[0];
    const float* w_op1  = (const float*)d_in[2];
    const float* b_op1  = (const float*)d_in[3];
    const float* w_op2  = (const float*)d_in[4];
    const float* b_op2  = (const float*)d_in[5];
    const float* w_num1 = (const float*)d_in[6];
    const float* b_num1 = (const float*)d_in[7];
    const float* w_num2 = (const float*)d_in[8];
    const float* b_num2 = (const float*)d_in[9];
    const float* w_ih   = (const float*)d_in[10];
    const float* b_ih   = (const float*)d_in[11];
    const float* w_hh   = (const float*)d_in[12];
    const float* b_hh   = (const float*)d_in[13];

    float* out = (float*)d_out;
    float* final_state = out;
    float* ops    = out + (size_t)Bb * Hh;
    float* nums   = ops + (size_t)Ss * Bb * 5;
    float* states = nums + (size_t)Ss * Bb;

    static bool attr_set = false;
    if (!attr_set) {
        cudaFuncSetAttribute(gemm_fused, cudaFuncAttributeMaxDynamicSharedMemorySize, SMEM_TOT);
        attr_set = true;
    }

    pack_w2<<<(NW * 1024) / 256, 256>>>(w_op1, w_num1, w_ih, w_hh);
    pack_misc<<<44, 256>>>(w_op2, b_op1, b_num1, b_ih, b_hh);
    convert_x<<<(Bb * Hh) / 256, 256>>>(x, states);

    // device-symbol addresses for the ping-pong A buffers
    __half* a2base = nullptr;
    cudaGetSymbolAddress((void**)&a2base, g_A2);

    for (int s = 0; s < Ss; s++) {
        float* ops_s  = ops + (size_t)s * Bb * 5;
        float* nums_s = nums + (size_t)s * Bb;
        init_heads<<<(Bb * 6) / 256, 256>>>(ops_s, nums_s, b_op2, b_num2);

        const __half* Ain = a2base + (size_t)(s & 1) * Bb * KTOT;
        __half* Aout      = a2base + (size_t)((s + 1) & 1) * Bb * KTOT;
        const float* h    = states + (size_t)s * Bb * Hh;
        float* h_out = (s == Ss - 1) ? final_state
                                     : states + (size_t)(s + 1) * Bb * Hh;

        dim3 ggrid(NW / BN, Bb / BM);   // (24, 128)
        gemm_fused<<<ggrid, NTHREADS, SMEM_TOT>>>(Ain, Aout, h, h_out, w_num2,
                                                  ops_s, nums_s);
    }
}

// round 10
// speedup vs baseline: 8.0465x; 1.0288x over previous
#include <cuda_runtime.h>
#include <cuda_fp16.h>
#include <cstdint>
#include <cstddef>

// Problem constants
#define Hh   1024
#define Bb   16384
#define Ss   8
#define NW   6144          // [op1 | num1 | gates interleaved 4*j+g]
#define KTOT 1024
#define NCHUNK 16          // KTOT / 64

#define BM 128
#define BN 128
#define STAGES      3
#define STAGE_BYTES 32768  // A 128x64 fp16 (16KB) + B 128x64 fp16 (16KB)
#define SMEM_TOT    (STAGES * STAGE_BYTES)
#define NTHREADS    256

// ---------------------------------------------------------------------------
// Device scratch
// ---------------------------------------------------------------------------
__device__ __half  g_W2[(size_t)NW * KTOT];      // 12.6 MB packed fp16 weights
__device__ __half  g_A2[2][(size_t)Bb * KTOT];   // ping-pong fp16 activations
__device__ float   g_Wop2t[5 * Hh];              // transposed op head weights
__device__ float   g_hb[2 * Hh];                 // [b_op1 | b_num1]
__device__ float   g_gb[4 * Hh];                 // interleaved gate biases

// ---------------------------------------------------------------------------
// Helpers
// ---------------------------------------------------------------------------
__device__ __forceinline__ float gelu_exact(float x) {
    return 0.5f * x * (1.0f + erff(x * 0.70710678118654752f));
}
__device__ __forceinline__ float fast_sig(float x) {
    return __fdividef(1.0f, 1.0f + __expf(-x));
}
__device__ __forceinline__ float fast_tanh(float x) {
    return __fdividef(2.0f, 1.0f + __expf(-2.0f * x)) - 1.0f;
}
__device__ __forceinline__ uint32_t smem_u32(const void* p) {
    uint32_t a;
    asm("{ .reg .u64 t; cvta.to.shared.u64 t, %1; cvt.u32.u64 %0, t; }" : "=r"(a) : "l"(p));
    return a;
}
__device__ __forceinline__ void cpasync16(uint32_t dst, const void* src) {
    asm volatile("cp.async.cg.shared.global [%0], [%1], 16;" :: "r"(dst), "l"(src) : "memory");
}
__device__ __forceinline__ void cp_commit() {
    asm volatile("cp.async.commit_group;" ::: "memory");
}
template <int N>
__device__ __forceinline__ void cp_wait() {
    asm volatile("cp.async.wait_group %0;" :: "n"(N) : "memory");
}
__device__ __forceinline__ void ldsm4(uint32_t* r, uint32_t addr) {
    asm volatile("ldmatrix.sync.aligned.m8n8.x4.shared.b16 {%0,%1,%2,%3}, [%4];"
                 : "=r"(r[0]), "=r"(r[1]), "=r"(r[2]), "=r"(r[3]) : "r"(addr));
}
__device__ __forceinline__ void mma_f16(float* c, const uint32_t* a, const uint32_t* b) {
    asm volatile(
        "mma.sync.aligned.m16n8k16.row.col.f32.f16.f16.f32 "
        "{%0,%1,%2,%3}, {%4,%5,%6,%7}, {%8,%9}, {%0,%1,%2,%3};"
        : "+f"(c[0]), "+f"(c[1]), "+f"(c[2]), "+f"(c[3])
        : "r"(a[0]), "r"(a[1]), "r"(a[2]), "r"(a[3]), "r"(b[0]), "r"(b[1]));
}
__device__ __forceinline__ uint32_t sw128(uint32_t off) {
    return off ^ ((off >> 3) & 0x70);
}

// ---------------------------------------------------------------------------
// Pack fp16 weights, gate-interleaved:
//   n<1024: op1^T; n<2048: num1^T;
//   n>=2048: j=(n-2048)>>2, g=n&3: [r_comb | z_comb | i_n | h_n]
// ---------------------------------------------------------------------------
__global__ void pack_w2(const float* __restrict__ w_op1, const float* __restrict__ w_num1,
                        const float* __restrict__ w_ih, const float* __restrict__ w_hh) {
    size_t idx = (size_t)blockIdx.x * 256 + threadIdx.x;   // over NW*1024
    int n = (int)(idx >> 10);
    int kk = (int)(idx & 1023);
    float v;
    if (n < 1024)      v = w_op1[(size_t)kk * Hh + n];
    else if (n < 2048) v = w_num1[(size_t)kk * Hh + (n - 1024)];
    else {
        int j = (n - 2048) >> 2;
        int g = n & 3;
        if (g == 0)      v = w_ih[(size_t)j * Hh + kk] + w_hh[(size_t)j * Hh + kk];
        else if (g == 1) v = w_ih[(size_t)(1024 + j) * Hh + kk] + w_hh[(size_t)(1024 + j) * Hh + kk];
        else if (g == 2) v = w_ih[(size_t)(2048 + j) * Hh + kk];
        else             v = w_hh[(size_t)(2048 + j) * Hh + kk];
    }
    g_W2[idx] = __float2half_rn(v);
}

// pack w_op2^T, head biases, interleaved gate biases
__global__ void pack_misc(const float* __restrict__ w_op2,
                          const float* __restrict__ b_op1, const float* __restrict__ b_num1,
                          const float* __restrict__ b_ih, const float* __restrict__ b_hh) {
    int idx = blockIdx.x * 256 + threadIdx.x;   // 0..11263
    if (idx < 5120) {
        int q = idx >> 10, c = idx & 1023;
        g_Wop2t[idx] = w_op2[(size_t)c * 5 + q];
    } else if (idx < 5120 + 2048) {
        int c = idx - 5120;
        g_hb[c] = (c < 1024) ? b_op1[c] : b_num1[c - 1024];
    } else if (idx < 5120 + 2048 + 4096) {
        int c = idx - 5120 - 2048;
        int j = c >> 2, g = c & 3;
        float v;
        if (g == 0)      v = b_ih[j] + b_hh[j];
        else if (g == 1) v = b_ih[1024 + j] + b_hh[1024 + j];
        else if (g == 2) v = b_ih[2048 + j];
        else             v = b_hh[2048 + j];
        g_gb[c] = v;
    }
}

// states[0] = x, and x -> g_A2[0] (fp16)
__global__ void convert_x(const float* __restrict__ x, float* __restrict__ states0) {
    size_t idx = (size_t)blockIdx.x * 256 + threadIdx.x;
    float h = x[idx];
    states0[idx] = h;
    g_A2[0][idx] = __float2half_rn(h);
}

// per-step: ops = b_op2 (broadcast), nums = b_num2
__global__ void init_heads(float* __restrict__ ops, float* __restrict__ nums,
                           const float* __restrict__ b_op2, const float* __restrict__ b_num2) {
    int idx = blockIdx.x * 256 + threadIdx.x;   // 0..98303
    if (idx < Bb * 5) ops[idx] = b_op2[idx % 5];
    else              nums[idx - Bb * 5] = b_num2[0];
}

// ---------------------------------------------------------------------------
// Fused HMMA GEMM + heads/GRU epilogue.
// BM=128, BN=128, BK=64. 256 threads = 8 warps (2 m x 4 n), warp tile 64x32.
// 3-stage cp.async pipeline, 2 CTAs/SM for bubble overlap.
// n-blocks: [0,8): op head; [8,16): num head; [16,48): gates.
// ---------------------------------------------------------------------------
__global__ void __launch_bounds__(NTHREADS, 2)
gemm_fused(const __half* __restrict__ Ain, __half* __restrict__ Aout,
           const float* __restrict__ h_in, float* __restrict__ h_out,
           const float* __restrict__ w_num2,
           float* __restrict__ ops, float* __restrict__ nums) {
    extern __shared__ char smem[];
    uint32_t sb = smem_u32(smem);
    int tid = threadIdx.x;
    int lane = tid & 31;
    int wid = tid >> 5;
    int n0 = blockIdx.x * BN;
    int m0 = blockIdx.y * BM;

    // ---- cp.async bases: 8 segs/thread (4 A + 4 B), strided by 32 rows ----
    int lrow = tid >> 3;            // 0..31
    int ls8 = tid & 7;
    uint32_t d0 = sw128((uint32_t)lrow * 128 + ls8 * 16);
    const char* pA0 = (const char*)(Ain + (size_t)(m0 + lrow) * KTOT) + ls8 * 16;
    const char* pB0 = (const char*)(g_W2 + (size_t)(n0 + lrow) * KTOT) + ls8 * 16;

    // ---- ldmatrix base offsets (ks=0); sw(off ^ ks*32) ----
    int wm = (wid >> 2) * 64;       // 0 or 64
    int wn = (wid & 3) * 32;        // 0..96
    uint32_t aoffb[4], boffb[2];
#pragma unroll
    for (int mi = 0; mi < 4; mi++)
        aoffb[mi] = sw128((uint32_t)(wm + mi * 16 + (lane & 15)) * 128 + ((lane >> 4) << 4));
#pragma unroll
    for (int nb = 0; nb < 2; nb++) {
        uint32_t rown = wn + nb * 16 + ((lane >> 4) & 1) * 8 + (lane & 7);
        boffb[nb] = sw128(rown * 128 + ((lane >> 3) & 1) * 16);
    }

    float cc[4][4][4];
#pragma unroll
    for (int mi = 0; mi < 4; mi++)
#pragma unroll
        for (int ni = 0; ni < 4; ni++)
#pragma unroll
            for (int q = 0; q < 4; q++) cc[mi][ni][q] = 0.0f;

    auto load_stage = [&](int st, int c) {
        uint32_t stb = sb + st * STAGE_BYTES;
        int kb = c * 128;
#pragma unroll
        for (int i = 0; i < 4; i++)
            cpasync16(stb + d0 + 4096 * i, pA0 + (size_t)i * 32 * (KTOT * 2) + kb);
#pragma unroll
        for (int i = 0; i < 4; i++)
            cpasync16(stb + 16384 + d0 + 4096 * i, pB0 + (size_t)i * 32 * (KTOT * 2) + kb);
    };

    // ---- prologue: 2 stages in flight ----
    load_stage(0, 0);
    cp_commit();
    load_stage(1, 1);
    cp_commit();

    // ---- main loop: one barrier per chunk ----
#pragma unroll 1
    for (int c = 0; c < NCHUNK; c++) {
        cp_wait<1>();
        __syncthreads();
        int s_ld = (c + 2) % STAGES;
        if (c + 2 < NCHUNK) load_stage(s_ld, c + 2);
        cp_commit();

        uint32_t stb = sb + (c % STAGES) * STAGE_BYTES;
#pragma unroll
        for (int ks = 0; ks < 4; ks++) {
            uint32_t kx = (uint32_t)ks * 32;
            uint32_t a[4][4];
#pragma unroll
            for (int mi = 0; mi < 4; mi++) ldsm4(a[mi], stb + (aoffb[mi] ^ kx));
            uint32_t b[4][2];
#pragma unroll
            for (int nb = 0; nb < 2; nb++) {
                uint32_t r[4];
                ldsm4(r, stb + 16384 + (boffb[nb] ^ kx));
                b[nb * 2][0] = r[0]; b[nb * 2][1] = r[1];
                b[nb * 2 + 1][0] = r[2]; b[nb * 2 + 1][1] = r[3];
            }
#pragma unroll
            for (int mi = 0; mi < 4; mi++)
#pragma unroll
                for (int ni = 0; ni < 4; ni++)
                    mma_f16(cc[mi][ni], a[mi], b[ni]);
        }
    }

    // ---- fused epilogue ----
    int mrow = m0 + wm + (lane >> 2);
    int cbase = n0 + wn + (lane & 3) * 2;

    if (blockIdx.x >= 16) {
        // ======== gate CTAs: GRU combine ========
        int odd = lane & 1;
#pragma unroll
        for (int ni = 0; ni < 4; ni++) {
            int col = cbase + ni * 8;
            int j = (col - 2048) >> 2;
            float b0 = g_gb[col - 2048];
            float b1 = g_gb[col - 2048 + 1];
#pragma unroll
            for (int mi = 0; mi < 4; mi++) {
#pragma unroll
                for (int hf = 0; hf < 2; hf++) {
                    float v0 = cc[mi][ni][hf * 2 + 0] + b0;
                    float v1 = cc[mi][ni][hf * 2 + 1] + b1;
                    float u0 = __shfl_xor_sync(0xffffffffu, v0, 1);
                    float u1 = __shfl_xor_sync(0xffffffffu, v1, 1);
                    float pre_r = odd ? u0 : v0;
                    float pre_z = odd ? u1 : v1;
                    float i_n   = odd ? v0 : u0;
                    float h_n   = odd ? v1 : u1;
                    float r = fast_sig(pre_r);
                    float z = fast_sig(pre_z);
                    float nn = fast_tanh(fmaf(r, h_n, i_n));
                    int row = mrow + mi * 16 + hf * 8;
                    size_t idx = (size_t)row * Hh + j;
                    float hold = h_in[idx];
                    float hnew = fmaf(z, hold - nn, nn);
                    if (!odd) h_out[idx] = hnew;
                    else      Aout[idx] = __float2half_rn(hnew);
                }
            }
        }
    } else if (blockIdx.x < 8) {
        // ======== op head CTAs: GELU + w_op2 partials ========
        float p[8][5];
#pragma unroll
        for (int ri = 0; ri < 8; ri++)
#pragma unroll
            for (int q = 0; q < 5; q++) p[ri][q] = 0.0f;
#pragma unroll
        for (int ni = 0; ni < 4; ni++) {
            int col = cbase + ni * 8;
            float b0 = g_hb[col], b1 = g_hb[col + 1];
            float w0[5], w1[5];
#pragma unroll
            for (int q = 0; q < 5; q++) {
                w0[q] = g_Wop2t[q * Hh + col];
                w1[q] = g_Wop2t[q * Hh + col + 1];
            }
#pragma unroll
            for (int mi = 0; mi < 4; mi++) {
#pragma unroll
                for (int hf = 0; hf < 2; hf++) {
                    float a0 = gelu_exact(cc[mi][ni][hf * 2 + 0] + b0);
                    float a1 = gelu_exact(cc[mi][ni][hf * 2 + 1] + b1);
                    int ri = mi * 2 + hf;
#pragma unroll
                    for (int q = 0; q < 5; q++)
                        p[ri][q] += a0 * w0[q] + a1 * w1[q];
                }
            }
        }
#pragma unroll
        for (int ri = 0; ri < 8; ri++)
#pragma unroll
            for (int q = 0; q < 5; q++) {
                p[ri][q] += __shfl_xor_sync(0xffffffffu, p[ri][q], 1);
                p[ri][q] += __shfl_xor_sync(0xffffffffu, p[ri][q], 2);
            }
        if ((lane & 3) == 0) {
#pragma unroll
            for (int ri = 0; ri < 8; ri++) {
                int row = mrow + (ri >> 1) * 16 + (ri & 1) * 8;
#pragma unroll
                for (int q = 0; q < 5; q++)
                    atomicAdd(&ops[(size_t)row * 5 + q], p[ri][q]);
            }
        }
    } else {
        // ======== num head CTAs ========
        float pn[8];
#pragma unroll
        for (int ri = 0; ri < 8; ri++) pn[ri] = 0.0f;
#pragma unroll
        for (int ni = 0; ni < 4; ni++) {
            int col = cbase + ni * 8;
            float b0 = g_hb[col], b1 = g_hb[col + 1];
            float w0 = w_num2[col - 1024], w1 = w_num2[col - 1024 + 1];
#pragma unroll
            for (int mi = 0; mi < 4; mi++) {
#pragma unroll
                for (int hf = 0; hf < 2; hf++) {
                    float a0 = gelu_exact(cc[mi][ni][hf * 2 + 0] + b0);
                    float a1 = gelu_exact(cc[mi][ni][hf * 2 + 1] + b1);
                    pn[mi * 2 + hf] += a0 * w0 + a1 * w1;
                }
            }
        }
#pragma unroll
        for (int ri = 0; ri < 8; ri++) {
            pn[ri] += __shfl_xor_sync(0xffffffffu, pn[ri], 1);
            pn[ri] += __shfl_xor_sync(0xffffffffu, pn[ri], 2);
        }
        if ((lane & 3) == 0) {
#pragma unroll
            for (int ri = 0; ri < 8; ri++) {
                int row = mrow + (ri >> 1) * 16 + (ri & 1) * 8;
                atomicAdd(&nums[row], pn[ri]);
            }
        }
    }
}

// ---------------------------------------------------------------------------
// Launch
// ---------------------------------------------------------------------------
extern "C" void kernel_launch(void* const* d_in, const int* in_sizes, int n_in,
                              void* d_out, int out_size) {
    const float* x      = (const float*)d_in[0];
    const float* w_op1  = (const float*)d_in[2];
    const float* b_op1  = (const float*)d_in[3];
    const float* w_op2  = (const float*)d_in[4];
    const float* b_op2  = (const float*)d_in[5];
    const float* w_num1 = (const float*)d_in[6];
    const float* b_num1 = (const float*)d_in[7];
    const float* w_num2 = (const float*)d_in[8];
    const float* b_num2 = (const float*)d_in[9];
    const float* w_ih   = (const float*)d_in[10];
    const float* b_ih   = (const float*)d_in[11];
    const float* w_hh   = (const float*)d_in[12];
    const float* b_hh   = (const float*)d_in[13];

    float* out = (float*)d_out;
    float* final_state = out;
    float* ops    = out + (size_t)Bb * Hh;
    float* nums   = ops + (size_t)Ss * Bb * 5;
    float* states = nums + (size_t)Ss * Bb;

    static bool attr_set = false;
    if (!attr_set) {
        cudaFuncSetAttribute(gemm_fused, cudaFuncAttributeMaxDynamicSharedMemorySize, SMEM_TOT);
        attr_set = true;
    }

    pack_w2<<<(NW * 1024) / 256, 256>>>(w_op1, w_num1, w_ih, w_hh);
    pack_misc<<<44, 256>>>(w_op2, b_op1, b_num1, b_ih, b_hh);
    convert_x<<<(Bb * Hh) / 256, 256>>>(x, states);

    __half* a2base = nullptr;
    cudaGetSymbolAddress((void**)&a2base, g_A2);

    for (int s = 0; s < Ss; s++) {
        float* ops_s  = ops + (size_t)s * Bb * 5;
        float* nums_s = nums + (size_t)s * Bb;
        init_heads<<<(Bb * 6) / 256, 256>>>(ops_s, nums_s, b_op2, b_num2);

        const __half* Ain = a2base + (size_t)(s & 1) * Bb * KTOT;
        __half* Aout      = a2base + (size_t)((s + 1) & 1) * Bb * KTOT;
        const float* h    = states + (size_t)s * Bb * Hh;
        float* h_out = (s == Ss - 1) ? final_state
                                     : states + (size_t)(s + 1) * Bb * Hh;

        dim3 ggrid(NW / BN, Bb / BM);   // (48, 128)
        gemm_fused<<<ggrid, NTHREADS, SMEM_TOT>>>(Ain, Aout, h, h_out, w_num2,
                                                  ops_s, nums_s);
    }
}